// round 1
// baseline (speedup 1.0000x reference)
#include <cuda_runtime.h>
#include <cuda_bf16.h>

// Problem constants
#define BB 8
#define SS 1024
#define IN_F 128
#define EE 512
#define HH 8
#define HD 64
#define FF_DIM 2048
#define NL 4
#define ROWS (BB*SS)          // 8192
#define EPS 1e-5f

// ---------------- scratch (device globals; no allocations allowed) ----------
__device__ __align__(16) float g_x[ROWS*EE];            // 16 MB
__device__ __align__(16) float g_qkv[ROWS*1024];        // 32 MB (q,k only)
__device__ __align__(16) float g_scores[(size_t)BB*HH*SS*SS]; // 256 MB
__device__ __align__(16) float g_w[(size_t)BB*SS*SS];   // 32 MB
__device__ __align__(16) float g_dbias[(size_t)BB*SS*SS];// 32 MB
__device__ __align__(16) float g_attn[ROWS*EE];         // 16 MB
__device__ __align__(16) float g_ff1[ROWS*FF_DIM];      // 64 MB
__device__ __align__(16) float g_part[2*64*EE];
__device__ __align__(16) float g_stats[2*EE];

// ---------------- generic tiled SGEMM --------------------------------------
// C[m,n] = alpha * sum_k A[m,k] * B(k,n) (+ bias[n]) (+relu)
// BT=true : B is [N,K] row-major (access B[n*ldb+k])   -> "NT"
// BT=false: B is [K,N] row-major (access B[k*ldb+n])   -> "NN"
// Batch: z in grid.z;  Az = A + (z/hdiv)*sA0 + (z%hdiv)*sA1  (same for B),
//        Cz = C + z*sC
#define BM 128
#define BN 128
#define BKK 16
#define TM 8
#define TN 8

template<bool BT, bool RELU>
__global__ __launch_bounds__(256) void gemm_k(
    const float* __restrict__ A, const float* __restrict__ B,
    const float* __restrict__ bias, float* __restrict__ C,
    int M, int N, int K, int lda, int ldb, int ldc,
    int hdiv, long long sA0, long long sA1, long long sB0, long long sB1,
    long long sC, float alpha)
{
    __shared__ float As[BKK][BM];
    __shared__ float Bs[BKK][BN];
    int z = blockIdx.z;
    const float* Ab = A + (long long)(z / hdiv) * sA0 + (long long)(z % hdiv) * sA1;
    const float* Bb = B + (long long)(z / hdiv) * sB0 + (long long)(z % hdiv) * sB1;
    float* Cb = C + (long long)z * sC;
    int m0 = blockIdx.y * BM, n0 = blockIdx.x * BN;
    int tid = threadIdx.x;
    float acc[TM][TN] = {};
    int ty = tid >> 4, tx = tid & 15;

    for (int k0 = 0; k0 < K; k0 += BKK) {
        // A tile: BM x BKK = 512 float4, 2 per thread (store transposed)
        #pragma unroll
        for (int i = 0; i < 2; i++) {
            int id = tid + i * 256;
            int row = id >> 2;
            int kv = (id & 3) * 4;
            float4 v = *(const float4*)&Ab[(long long)(m0 + row) * lda + k0 + kv];
            As[kv+0][row] = v.x; As[kv+1][row] = v.y;
            As[kv+2][row] = v.z; As[kv+3][row] = v.w;
        }
        if (BT) {
            #pragma unroll
            for (int i = 0; i < 2; i++) {
                int id = tid + i * 256;
                int row = id >> 2;           // n index
                int kv = (id & 3) * 4;
                float4 v = *(const float4*)&Bb[(long long)(n0 + row) * ldb + k0 + kv];
                Bs[kv+0][row] = v.x; Bs[kv+1][row] = v.y;
                Bs[kv+2][row] = v.z; Bs[kv+3][row] = v.w;
            }
        } else {
            #pragma unroll
            for (int i = 0; i < 2; i++) {
                int id = tid + i * 256;
                int krow = id >> 5;          // 0..15
                int nv = (id & 31) * 4;
                float4 v = *(const float4*)&Bb[(long long)(k0 + krow) * ldb + n0 + nv];
                *(float4*)&Bs[krow][nv] = v;
            }
        }
        __syncthreads();
        #pragma unroll
        for (int kk = 0; kk < BKK; kk++) {
            float a[TM], b[TN];
            #pragma unroll
            for (int i = 0; i < TM; i++) a[i] = As[kk][ty*TM+i];
            #pragma unroll
            for (int j = 0; j < TN; j++) b[j] = Bs[kk][tx*TN+j];
            #pragma unroll
            for (int i = 0; i < TM; i++)
                #pragma unroll
                for (int j = 0; j < TN; j++)
                    acc[i][j] += a[i] * b[j];
        }
        __syncthreads();
    }
    #pragma unroll
    for (int i = 0; i < TM; i++) {
        int row = m0 + ty*TM + i;
        #pragma unroll
        for (int j = 0; j < TN; j++) {
            int col = n0 + tx*TN + j;
            float v = acc[i][j] * alpha;
            if (bias) v += bias[col];
            if (RELU) v = fmaxf(v, 0.f);
            Cb[(long long)row * ldc + col] = v;
        }
    }
}

// ---------------- BatchNorm (training-mode batch stats), deterministic -----
__global__ void bn_part_k(const float* __restrict__ x, float* __restrict__ part) {
    int e = threadIdx.x;            // 512 threads
    int blk = blockIdx.x;           // 64 blocks, 128 rows each
    float s = 0.f, sq = 0.f;
    int r0 = blk * 128;
    for (int r = r0; r < r0 + 128; r++) {
        float v = x[(long long)r * EE + e];
        s += v; sq += v * v;
    }
    part[blk * EE + e] = s;
    part[(64 + blk) * EE + e] = sq;
}

__global__ void bn_final_k(const float* __restrict__ part, float* __restrict__ stats) {
    int e = blockIdx.x * blockDim.x + threadIdx.x;  // 512 total
    float s = 0.f, sq = 0.f;
    for (int i = 0; i < 64; i++) {
        s  += part[i * EE + e];
        sq += part[(64 + i) * EE + e];
    }
    float mu = s / (float)ROWS;
    stats[e] = mu;
    stats[EE + e] = sq / (float)ROWS - mu * mu;
}

// BN apply + positional encoding (computed analytically)
__global__ void bn_apply_pe_k(float* __restrict__ x, const float* __restrict__ stats,
                              const float* __restrict__ g, const float* __restrict__ b) {
    long long idx = (long long)blockIdx.x * blockDim.x + threadIdx.x;
    int e = (int)(idx & (EE - 1));
    long long r = idx >> 9;
    int s = (int)(r & (SS - 1));
    float mu = stats[e], var = stats[EE + e];
    int j = e >> 1;
    float dt = expf((float)(2 * j) * (-9.210340371976184f / (float)EE)); // -ln(10000)/E
    float ang = (float)s * dt;
    float pe = (e & 1) ? cosf(ang) : sinf(ang);
    x[idx] = (x[idx] - mu) * rsqrtf(var + EPS) * g[e] + b[e] + pe;
}

// ---------------- distance bias: exp(scale * (1 - d / rowmax(d))) ----------
__global__ void dist_bias_k(const float* __restrict__ d, const float* __restrict__ scale_p,
                            float* __restrict__ bias) {
    int bq = blockIdx.x;                 // 0..8191 (b*S + q)
    const float* dp = d + (long long)bq * SS;
    __shared__ float red[256];
    int tid = threadIdx.x;
    float lv[4];
    float lmax = -1e30f;
    #pragma unroll
    for (int i = 0; i < 4; i++) { lv[i] = dp[tid + i * 256]; lmax = fmaxf(lmax, lv[i]); }
    red[tid] = lmax; __syncthreads();
    for (int s = 128; s > 0; s >>= 1) {
        if (tid < s) red[tid] = fmaxf(red[tid], red[tid + s]);
        __syncthreads();
    }
    float inv_dmax = 1.f / red[0];
    float sc = scale_p[0];
    float* bp = bias + (long long)bq * SS;
    #pragma unroll
    for (int i = 0; i < 4; i++)
        bp[tid + i * 256] = expf(sc * (1.f - lv[i] * inv_dmax));
}

// ---------------- softmax per head, head-avg, * dist_bias, renormalize -----
__global__ void attn_w_k(const float* __restrict__ scores, const float* __restrict__ dbias,
                         float* __restrict__ w) {
    int bq = blockIdx.x;
    int b = bq >> 10, q = bq & (SS - 1);
    __shared__ float row[SS];
    __shared__ float acc[SS];
    __shared__ float red[256];
    int tid = threadIdx.x;
    for (int i = tid; i < SS; i += 256) acc[i] = 0.f;
    __syncthreads();
    for (int h = 0; h < HH; h++) {
        const float* sp = scores + ((long long)(b * HH + h) * SS + q) * SS;
        float lv[4];
        float lmax = -1e30f;
        #pragma unroll
        for (int i = 0; i < 4; i++) { lv[i] = sp[tid + i * 256]; lmax = fmaxf(lmax, lv[i]); }
        red[tid] = lmax; __syncthreads();
        for (int s = 128; s > 0; s >>= 1) {
            if (tid < s) red[tid] = fmaxf(red[tid], red[tid + s]);
            __syncthreads();
        }
        float mx = red[0]; __syncthreads();
        float lsum = 0.f;
        #pragma unroll
        for (int i = 0; i < 4; i++) {
            float e = __expf(lv[i] - mx);
            row[tid + i * 256] = e;
            lsum += e;
        }
        red[tid] = lsum; __syncthreads();
        for (int s = 128; s > 0; s >>= 1) {
            if (tid < s) red[tid] += red[tid + s];
            __syncthreads();
        }
        float inv = 1.f / red[0]; __syncthreads();
        #pragma unroll
        for (int i = 0; i < 4; i++)
            acc[tid + i * 256] += row[tid + i * 256] * inv;
        __syncthreads();
    }
    // multiply by distance bias, renormalize over k
    const float* bp = dbias + (long long)bq * SS;
    float wv[4];
    float lsum = 0.f;
    #pragma unroll
    for (int i = 0; i < 4; i++) {
        wv[i] = acc[tid + i * 256] * bp[tid + i * 256];
        lsum += wv[i];
    }
    red[tid] = lsum; __syncthreads();
    for (int s = 128; s > 0; s >>= 1) {
        if (tid < s) red[tid] += red[tid + s];
        __syncthreads();
    }
    float inv = 1.f / red[0];
    float* wp = w + (long long)bq * SS;
    #pragma unroll
    for (int i = 0; i < 4; i++)
        wp[tid + i * 256] = wv[i] * inv;
}

// ---------------- fused residual + LayerNorm --------------------------------
__global__ void add_ln_k(const float* __restrict__ x, const float* __restrict__ r,
                         const float* __restrict__ g, const float* __restrict__ b,
                         float* __restrict__ out) {
    int row = blockIdx.x;
    int tid = threadIdx.x;
    __shared__ float red[256];
    long long base = (long long)row * EE;
    float v0 = x[base + tid]       + r[base + tid];
    float v1 = x[base + tid + 256] + r[base + tid + 256];
    red[tid] = v0 + v1; __syncthreads();
    for (int s = 128; s > 0; s >>= 1) {
        if (tid < s) red[tid] += red[tid + s];
        __syncthreads();
    }
    float mean = red[0] / (float)EE; __syncthreads();
    red[tid] = v0 * v0 + v1 * v1; __syncthreads();
    for (int s = 128; s > 0; s >>= 1) {
        if (tid < s) red[tid] += red[tid + s];
        __syncthreads();
    }
    float var = red[0] / (float)EE - mean * mean;
    float inv = rsqrtf(var + EPS);
    out[base + tid]       = (v0 - mean) * inv * g[tid]       + b[tid];
    out[base + tid + 256] = (v1 - mean) * inv * g[tid + 256] + b[tid + 256];
}

// ---------------- launch -----------------------------------------------------
extern "C" void kernel_launch(void* const* d_in, const int* in_sizes, int n_in,
                              void* d_out, int out_size) {
    (void)in_sizes; (void)n_in; (void)out_size;
    const float* src        = (const float*)d_in[0];
    const float* distances  = (const float*)d_in[1];
    const float* proj_w     = (const float*)d_in[2];
    const float* proj_b     = (const float*)d_in[3];
    const float* bn_g       = (const float*)d_in[4];
    const float* bn_b       = (const float*)d_in[5];
    const float* in_proj_w  = (const float*)d_in[6];
    const float* in_proj_b  = (const float*)d_in[7];
    const float* dist_scale = (const float*)d_in[8];
    const float* lin1_w     = (const float*)d_in[9];
    const float* lin1_b     = (const float*)d_in[10];
    const float* lin2_w     = (const float*)d_in[11];
    const float* lin2_b     = (const float*)d_in[12];
    const float* n1_g       = (const float*)d_in[13];
    const float* n1_b       = (const float*)d_in[14];
    const float* n2_g       = (const float*)d_in[15];
    const float* n2_b       = (const float*)d_in[16];
    float* out = (float*)d_out;

    float *x, *qkv, *sc, *w, *dbias, *attn, *ff1, *part, *stats;
    cudaGetSymbolAddress((void**)&x,     g_x);
    cudaGetSymbolAddress((void**)&qkv,   g_qkv);
    cudaGetSymbolAddress((void**)&sc,    g_scores);
    cudaGetSymbolAddress((void**)&w,     g_w);
    cudaGetSymbolAddress((void**)&dbias, g_dbias);
    cudaGetSymbolAddress((void**)&attn,  g_attn);
    cudaGetSymbolAddress((void**)&ff1,   g_ff1);
    cudaGetSymbolAddress((void**)&part,  g_part);
    cudaGetSymbolAddress((void**)&stats, g_stats);

    dim3 blk(256);
    const long long SE  = (long long)SS * EE;       // 524288
    const long long SQ  = (long long)SS * 1024;     // qkv row-block stride per batch
    const long long SS2 = (long long)SS * SS;       // 1048576

    // 1) input projection: [8192,128] @ [512,128]^T -> g_x
    gemm_k<true,false><<<dim3(EE/BN, ROWS/BM, 1), blk>>>(
        src, proj_w, proj_b, x, ROWS, EE, IN_F, IN_F, IN_F, EE,
        1, 0, 0, 0, 0, 0, 1.f);

    // 2) BatchNorm (batch stats) + PE
    bn_part_k<<<64, 512>>>(x, part);
    bn_final_k<<<2, 256>>>(part, stats);
    bn_apply_pe_k<<<(ROWS*EE)/256, 256>>>(x, stats, bn_g, bn_b);

    // 3) distance bias (shared across layers)
    dist_bias_k<<<BB*SS, 256>>>(distances, dist_scale, dbias);

    // 4) layers (shared parameters)
    for (int l = 0; l < NL; l++) {
        // qk = x @ in_proj_w[0:1024]^T  (V is unused by the reference)
        gemm_k<true,false><<<dim3(1024/BN, ROWS/BM, 1), blk>>>(
            x, in_proj_w, in_proj_b, qkv, ROWS, 1024, EE, EE, EE, 1024,
            1, 0, 0, 0, 0, 0, 1.f);

        // scores[b,h] = (Q_bh @ K_bh^T) * 1/sqrt(HD); batch z=(b*H+h)
        gemm_k<true,false><<<dim3(SS/BN, SS/BM, BB*HH), blk>>>(
            qkv, qkv + EE, nullptr, sc, SS, SS, HD, 1024, 1024, SS,
            HH, SQ, HD, SQ, HD, SS2, 0.125f);

        // per-row: softmax each head, head-average, * dist_bias, renormalize
        attn_w_k<<<BB*SS, 256>>>(sc, dbias, w);

        // attn_out = w @ x (value = raw layer input); batch over b, NN layout
        gemm_k<false,false><<<dim3(EE/BN, SS/BM, BB), blk>>>(
            w, x, nullptr, attn, SS, EE, SS, SS, EE, EE,
            1, SS2, 0, SE, 0, SE, 1.f);

        // x = LN(x + attn_out)
        add_ln_k<<<ROWS, 256>>>(x, attn, n1_g, n1_b, x);

        // FFN
        gemm_k<true,true><<<dim3(FF_DIM/BN, ROWS/BM, 1), blk>>>(
            x, lin1_w, lin1_b, ff1, ROWS, FF_DIM, EE, EE, EE, FF_DIM,
            1, 0, 0, 0, 0, 0, 1.f);
        gemm_k<true,false><<<dim3(EE/BN, ROWS/BM, 1), blk>>>(
            ff1, lin2_w, lin2_b, attn, ROWS, EE, FF_DIM, FF_DIM, FF_DIM, EE,
            1, 0, 0, 0, 0, 0, 1.f);

        // x = LN(x + ff); last layer writes straight to d_out
        add_ln_k<<<ROWS, 256>>>(x, attn, n2_g, n2_b, (l == NL - 1) ? out : x);
    }
}

// round 3
// speedup vs baseline: 2.0705x; 2.0705x over previous
#include <cuda_runtime.h>
#include <cuda_fp16.h>
#include <cstdint>

// Problem constants
#define BB 8
#define SS 1024
#define IN_F 128
#define EE 512
#define HH 8
#define HD 64
#define FF_DIM 2048
#define NL 4
#define ROWS (BB*SS)          // 8192
#define EPS 1e-5f

// ---------------- scratch (device globals; no allocations allowed) ----------
__device__ __align__(16) float g_x[ROWS*EE];            // 16 MB
__device__ __align__(16) float g_qkv[ROWS*1024];        // 32 MB (q,k only)
__device__ __align__(16) float g_scores[(size_t)BB*HH*SS*SS]; // 256 MB
__device__ __align__(16) float g_w[(size_t)BB*SS*SS];   // 32 MB
__device__ __align__(16) float g_dbias[(size_t)BB*SS*SS];// 32 MB
__device__ __align__(16) float g_attn[ROWS*EE];         // 16 MB
__device__ __align__(16) float g_ff1[ROWS*FF_DIM];      // 64 MB
__device__ __align__(16) float g_part[2*64*EE];
__device__ __align__(16) float g_stats[2*EE];

// ====================== helpers =============================================
__device__ __forceinline__ uint32_t smem_u32(const void* p){
    uint32_t a;
    asm("{ .reg .u64 t; cvta.to.shared.u64 t, %1; cvt.u32.u64 %0, t; }"
        : "=r"(a) : "l"(p));
    return a;
}
__device__ __forceinline__ void ldsm4(uint32_t& r0, uint32_t& r1, uint32_t& r2, uint32_t& r3,
                                      uint32_t addr){
    asm volatile("ldmatrix.sync.aligned.m8n8.x4.shared.b16 {%0,%1,%2,%3}, [%4];"
                 : "=r"(r0), "=r"(r1), "=r"(r2), "=r"(r3) : "r"(addr));
}
__device__ __forceinline__ void mma16816(float* c, const uint32_t* a, const uint32_t* b){
    asm volatile("mma.sync.aligned.m16n8k16.row.col.f32.f16.f16.f32 "
                 "{%0,%1,%2,%3}, {%4,%5,%6,%7}, {%8,%9}, {%0,%1,%2,%3};"
                 : "+f"(c[0]), "+f"(c[1]), "+f"(c[2]), "+f"(c[3])
                 : "r"(a[0]), "r"(a[1]), "r"(a[2]), "r"(a[3]), "r"(b[0]), "r"(b[1]));
}
// Split float4 into fp16 hi / fp16 lo residual, packed as uint2 (4 halves each)
__device__ __forceinline__ void split4(float4 v, uint2& h, uint2& l){
    __half2 h0 = __floats2half2_rn(v.x, v.y);
    __half2 h1 = __floats2half2_rn(v.z, v.w);
    float2 f0 = __half22float2(h0), f1 = __half22float2(h1);
    __half2 l0 = __floats2half2_rn(v.x - f0.x, v.y - f0.y);
    __half2 l1 = __floats2half2_rn(v.z - f1.x, v.w - f1.y);
    h.x = *reinterpret_cast<uint32_t*>(&h0);
    h.y = *reinterpret_cast<uint32_t*>(&h1);
    l.x = *reinterpret_cast<uint32_t*>(&l0);
    l.y = *reinterpret_cast<uint32_t*>(&l1);
}

// ====================== fp16x3 mma.sync GEMM ================================
// C[m,n] = alpha * sum_k A[m,k]*B(k,n) (+bias[n]) (+relu)
// BT=true : B is [N,K] row-major (NT).  BT=false: B is [K,N] row-major (NN).
// Batch: z; Ab = A + (z/hdiv)*sA0 + (z%hdiv)*sA1 (same for B), Cb = C + z*sC.
// CTA tile 128x128, BK=32. smem per stage: Ah|Al|Bh|Bl, each 128x32 fp16 (8KB),
// row pitch 64B, 16B-group swizzle: g ^= (row>>1)&3. Double buffered (64KB).
#define GEMM_SMEM (2*32768)

template<bool BT, bool RELU>
__global__ __launch_bounds__(256) void gemm_mma(
    const float* __restrict__ A, const float* __restrict__ B,
    const float* __restrict__ bias, float* __restrict__ C,
    int K, int lda, int ldb, int ldc,
    int hdiv, long long sA0, long long sA1, long long sB0, long long sB1,
    long long sC, float alpha)
{
    extern __shared__ char sm[];
    int tid = threadIdx.x, lane = tid & 31, wid = tid >> 5;
    int z = blockIdx.z;
    const float* Ab = A + (long long)(z / hdiv) * sA0 + (long long)(z % hdiv) * sA1;
    const float* Bb = B + (long long)(z / hdiv) * sB0 + (long long)(z % hdiv) * sB1;
    float* Cb = C + (long long)z * sC;
    int m0 = blockIdx.y * 128, n0 = blockIdx.x * 128;
    int wm0 = (wid >> 2) * 64, wn0 = (wid & 3) * 32;

    float acc[4][4][4];
    #pragma unroll
    for (int i = 0; i < 4; i++)
        #pragma unroll
        for (int j = 0; j < 4; j++)
            #pragma unroll
            for (int e = 0; e < 4; e++) acc[i][j][e] = 0.f;

    uint32_t smBase = smem_u32(sm);
    // per-lane ldmatrix address components
    int lm = lane & 15;
    uint32_t aRowB = (uint32_t)(wm0 + lm) * 64;        // + mt*16*64
    uint32_t aXor  = (lm >> 1) & 3;
    uint32_t aG    = (uint32_t)(lane >> 4);            // + ks*2
    uint32_t bRowB = (uint32_t)(wn0 + ((lane >> 4) << 3) + (lane & 7)) * 64;  // + ntp*16*64
    uint32_t bXor  = ((lane & 7) >> 1) & 3;
    uint32_t bG    = (uint32_t)((lane >> 3) & 1);

    int nch = K >> 5;
    float4 rA[4], rB[4];

    // prefetch chunk 0
    #pragma unroll
    for (int j = 0; j < 4; j++) {
        int id = tid + j * 256; int r = id >> 3, c4 = id & 7;
        rA[j] = *(const float4*)(Ab + (long long)(m0 + r) * lda + c4 * 4);
    }
    if (BT) {
        #pragma unroll
        for (int j = 0; j < 4; j++) {
            int id = tid + j * 256; int r = id >> 3, c4 = id & 7;
            rB[j] = *(const float4*)(Bb + (long long)(n0 + r) * ldb + c4 * 4);
        }
    } else {
        #pragma unroll
        for (int j = 0; j < 4; j++) {
            int id = tid + j * 256; int k = id >> 5, n4 = id & 31;
            rB[j] = *(const float4*)(Bb + (long long)k * ldb + n0 + n4 * 4);
        }
    }

    for (int c = 0; c < nch; c++) {
        int st = c & 1;
        char* buf = sm + st * 32768;            // Ah | Al(+8192) | Bh(+16384) | Bl(+24576)
        // ---- stage A ----
        #pragma unroll
        for (int j = 0; j < 4; j++) {
            int id = tid + j * 256; int r = id >> 3, c4 = id & 7;
            uint32_t off = (uint32_t)(r * 64 + (((c4 >> 1) ^ ((r >> 1) & 3)) << 4) + (c4 & 1) * 8);
            uint2 h, l; split4(rA[j], h, l);
            *(uint2*)(buf + off) = h;
            *(uint2*)(buf + 8192 + off) = l;
        }
        // ---- stage B ----
        if (BT) {
            #pragma unroll
            for (int j = 0; j < 4; j++) {
                int id = tid + j * 256; int r = id >> 3, c4 = id & 7;
                uint32_t off = (uint32_t)(r * 64 + (((c4 >> 1) ^ ((r >> 1) & 3)) << 4) + (c4 & 1) * 8);
                uint2 h, l; split4(rB[j], h, l);
                *(uint2*)(buf + 16384 + off) = h;
                *(uint2*)(buf + 24576 + off) = l;
            }
        } else {
            #pragma unroll
            for (int j = 0; j < 4; j++) {
                int id = tid + j * 256; int k = id >> 5, n4 = id & 31;
                float vv[4] = {rB[j].x, rB[j].y, rB[j].z, rB[j].w};
                #pragma unroll
                for (int e = 0; e < 4; e++) {
                    int n = n4 * 4 + e;
                    uint32_t off = (uint32_t)(n * 64 + (((k >> 3) ^ ((n >> 1) & 3)) << 4) + (k & 7) * 2);
                    __half hv = __float2half_rn(vv[e]);
                    __half lv = __float2half_rn(vv[e] - __half2float(hv));
                    *(__half*)(buf + 16384 + off) = hv;
                    *(__half*)(buf + 24576 + off) = lv;
                }
            }
        }
        // ---- prefetch next chunk ----
        if (c + 1 < nch) {
            int k0 = (c + 1) * 32;
            #pragma unroll
            for (int j = 0; j < 4; j++) {
                int id = tid + j * 256; int r = id >> 3, c4 = id & 7;
                rA[j] = *(const float4*)(Ab + (long long)(m0 + r) * lda + k0 + c4 * 4);
            }
            if (BT) {
                #pragma unroll
                for (int j = 0; j < 4; j++) {
                    int id = tid + j * 256; int r = id >> 3, c4 = id & 7;
                    rB[j] = *(const float4*)(Bb + (long long)(n0 + r) * ldb + k0 + c4 * 4);
                }
            } else {
                #pragma unroll
                for (int j = 0; j < 4; j++) {
                    int id = tid + j * 256; int k = id >> 5, n4 = id & 31;
                    rB[j] = *(const float4*)(Bb + (long long)(k0 + k) * ldb + n0 + n4 * 4);
                }
            }
        }
        __syncthreads();
        // ---- compute: 2 k-steps of 16 ----
        uint32_t base = smBase + st * 32768;
        #pragma unroll
        for (int ks = 0; ks < 2; ks++) {
            uint32_t bh[8], bl[8];
            #pragma unroll
            for (int ntp = 0; ntp < 2; ntp++) {
                uint32_t ga = (uint32_t)(ks * 2) + bG;
                uint32_t off = bRowB + (uint32_t)(ntp * 1024) + ((ga ^ bXor) << 4);
                ldsm4(bh[ntp*4+0], bh[ntp*4+1], bh[ntp*4+2], bh[ntp*4+3], base + 16384 + off);
                ldsm4(bl[ntp*4+0], bl[ntp*4+1], bl[ntp*4+2], bl[ntp*4+3], base + 24576 + off);
            }
            #pragma unroll
            for (int mt = 0; mt < 4; mt++) {
                uint32_t ga = (uint32_t)(ks * 2) + aG;
                uint32_t off = aRowB + (uint32_t)(mt * 1024) + ((ga ^ aXor) << 4);
                uint32_t ah[4], al[4];
                ldsm4(ah[0], ah[1], ah[2], ah[3], base + off);
                ldsm4(al[0], al[1], al[2], al[3], base + 8192 + off);
                #pragma unroll
                for (int nt = 0; nt < 4; nt++) {
                    const uint32_t* ph = &bh[(nt >> 1) * 4 + (nt & 1) * 2];
                    const uint32_t* pl = &bl[(nt >> 1) * 4 + (nt & 1) * 2];
                    mma16816(acc[mt][nt], ah, ph);
                    mma16816(acc[mt][nt], ah, pl);
                    mma16816(acc[mt][nt], al, ph);
                }
            }
        }
        __syncthreads();
    }

    // ---- epilogue: direct float2 stores, fused alpha/bias/relu ----
    #pragma unroll
    for (int nt = 0; nt < 4; nt++) {
        int cc = n0 + wn0 + nt * 8 + (lane & 3) * 2;
        float b0 = 0.f, b1 = 0.f;
        if (bias) { b0 = bias[cc]; b1 = bias[cc + 1]; }
        #pragma unroll
        for (int mt = 0; mt < 4; mt++) {
            int r = m0 + wm0 + mt * 16 + (lane >> 2);
            float v0 = acc[mt][nt][0] * alpha + b0;
            float v1 = acc[mt][nt][1] * alpha + b1;
            float v2 = acc[mt][nt][2] * alpha + b0;
            float v3 = acc[mt][nt][3] * alpha + b1;
            if (RELU) { v0 = fmaxf(v0,0.f); v1 = fmaxf(v1,0.f); v2 = fmaxf(v2,0.f); v3 = fmaxf(v3,0.f); }
            *(float2*)(Cb + (long long)r * ldc + cc)       = make_float2(v0, v1);
            *(float2*)(Cb + (long long)(r + 8) * ldc + cc) = make_float2(v2, v3);
        }
    }
}

// ---------------- BatchNorm (training-mode batch stats), deterministic -----
__global__ void bn_part_k(const float* __restrict__ x, float* __restrict__ part) {
    int e = threadIdx.x;
    int blk = blockIdx.x;
    float s = 0.f, sq = 0.f;
    int r0 = blk * 128;
    for (int r = r0; r < r0 + 128; r++) {
        float v = x[(long long)r * EE + e];
        s += v; sq += v * v;
    }
    part[blk * EE + e] = s;
    part[(64 + blk) * EE + e] = sq;
}

__global__ void bn_final_k(const float* __restrict__ part, float* __restrict__ stats) {
    int e = blockIdx.x * blockDim.x + threadIdx.x;
    float s = 0.f, sq = 0.f;
    for (int i = 0; i < 64; i++) {
        s  += part[i * EE + e];
        sq += part[(64 + i) * EE + e];
    }
    float mu = s / (float)ROWS;
    stats[e] = mu;
    stats[EE + e] = sq / (float)ROWS - mu * mu;
}

__global__ void bn_apply_pe_k(float* __restrict__ x, const float* __restrict__ stats,
                              const float* __restrict__ g, const float* __restrict__ b) {
    long long idx = (long long)blockIdx.x * blockDim.x + threadIdx.x;
    int e = (int)(idx & (EE - 1));
    long long r = idx >> 9;
    int s = (int)(r & (SS - 1));
    float mu = stats[e], var = stats[EE + e];
    int j = e >> 1;
    float dt = expf((float)(2 * j) * (-9.210340371976184f / (float)EE));
    float ang = (float)s * dt;
    float pe = (e & 1) ? cosf(ang) : sinf(ang);
    x[idx] = (x[idx] - mu) * rsqrtf(var + EPS) * g[e] + b[e] + pe;
}

// ---------------- distance bias ---------------------------------------------
__global__ void dist_bias_k(const float* __restrict__ d, const float* __restrict__ scale_p,
                            float* __restrict__ bias) {
    int bq = blockIdx.x;
    const float* dp = d + (long long)bq * SS;
    __shared__ float red[256];
    int tid = threadIdx.x;
    float lv[4];
    float lmax = -1e30f;
    #pragma unroll
    for (int i = 0; i < 4; i++) { lv[i] = dp[tid + i * 256]; lmax = fmaxf(lmax, lv[i]); }
    red[tid] = lmax; __syncthreads();
    for (int s = 128; s > 0; s >>= 1) {
        if (tid < s) red[tid] = fmaxf(red[tid], red[tid + s]);
        __syncthreads();
    }
    float inv_dmax = 1.f / red[0];
    float sc = scale_p[0];
    float* bp = bias + (long long)bq * SS;
    #pragma unroll
    for (int i = 0; i < 4; i++)
        bp[tid + i * 256] = expf(sc * (1.f - lv[i] * inv_dmax));
}

// ---------------- softmax per head, head-avg, * dist_bias, renormalize -----
__global__ void attn_w_k(const float* __restrict__ scores, const float* __restrict__ dbias,
                         float* __restrict__ w) {
    int bq = blockIdx.x;
    int b = bq >> 10, q = bq & (SS - 1);
    __shared__ float row[SS];
    __shared__ float acc[SS];
    __shared__ float red[256];
    int tid = threadIdx.x;
    for (int i = tid; i < SS; i += 256) acc[i] = 0.f;
    __syncthreads();
    for (int h = 0; h < HH; h++) {
        const float* sp = scores + ((long long)(b * HH + h) * SS + q) * SS;
        float lv[4];
        float lmax = -1e30f;
        #pragma unroll
        for (int i = 0; i < 4; i++) { lv[i] = sp[tid + i * 256]; lmax = fmaxf(lmax, lv[i]); }
        red[tid] = lmax; __syncthreads();
        for (int s = 128; s > 0; s >>= 1) {
            if (tid < s) red[tid] = fmaxf(red[tid], red[tid + s]);
            __syncthreads();
        }
        float mx = red[0]; __syncthreads();
        float lsum = 0.f;
        #pragma unroll
        for (int i = 0; i < 4; i++) {
            float e = __expf(lv[i] - mx);
            row[tid + i * 256] = e;
            lsum += e;
        }
        red[tid] = lsum; __syncthreads();
        for (int s = 128; s > 0; s >>= 1) {
            if (tid < s) red[tid] += red[tid + s];
            __syncthreads();
        }
        float inv = 1.f / red[0]; __syncthreads();
        #pragma unroll
        for (int i = 0; i < 4; i++)
            acc[tid + i * 256] += row[tid + i * 256] * inv;
        __syncthreads();
    }
    const float* bp = dbias + (long long)bq * SS;
    float wv[4];
    float lsum = 0.f;
    #pragma unroll
    for (int i = 0; i < 4; i++) {
        wv[i] = acc[tid + i * 256] * bp[tid + i * 256];
        lsum += wv[i];
    }
    red[tid] = lsum; __syncthreads();
    for (int s = 128; s > 0; s >>= 1) {
        if (tid < s) red[tid] += red[tid + s];
        __syncthreads();
    }
    float inv = 1.f / red[0];
    float* wp = w + (long long)bq * SS;
    #pragma unroll
    for (int i = 0; i < 4; i++)
        wp[tid + i * 256] = wv[i] * inv;
}

// ---------------- fused residual + LayerNorm --------------------------------
__global__ void add_ln_k(const float* __restrict__ x, const float* __restrict__ r,
                         const float* __restrict__ g, const float* __restrict__ b,
                         float* __restrict__ out) {
    int row = blockIdx.x;
    int tid = threadIdx.x;
    __shared__ float red[256];
    long long base = (long long)row * EE;
    float v0 = x[base + tid]       + r[base + tid];
    float v1 = x[base + tid + 256] + r[base + tid + 256];
    red[tid] = v0 + v1; __syncthreads();
    for (int s = 128; s > 0; s >>= 1) {
        if (tid < s) red[tid] += red[tid + s];
        __syncthreads();
    }
    float mean = red[0] / (float)EE; __syncthreads();
    red[tid] = v0 * v0 + v1 * v1; __syncthreads();
    for (int s = 128; s > 0; s >>= 1) {
        if (tid < s) red[tid] += red[tid + s];
        __syncthreads();
    }
    float var = red[0] / (float)EE - mean * mean;
    float inv = rsqrtf(var + EPS);
    out[base + tid]       = (v0 - mean) * inv * g[tid]       + b[tid];
    out[base + tid + 256] = (v1 - mean) * inv * g[tid + 256] + b[tid + 256];
}

// ---------------- launch -----------------------------------------------------
extern "C" void kernel_launch(void* const* d_in, const int* in_sizes, int n_in,
                              void* d_out, int out_size) {
    (void)in_sizes; (void)n_in; (void)out_size;
    const float* src        = (const float*)d_in[0];
    const float* distances  = (const float*)d_in[1];
    const float* proj_w     = (const float*)d_in[2];
    const float* proj_b     = (const float*)d_in[3];
    const float* bn_g       = (const float*)d_in[4];
    const float* bn_b       = (const float*)d_in[5];
    const float* in_proj_w  = (const float*)d_in[6];
    const float* in_proj_b  = (const float*)d_in[7];
    const float* dist_scale = (const float*)d_in[8];
    const float* lin1_w     = (const float*)d_in[9];
    const float* lin1_b     = (const float*)d_in[10];
    const float* lin2_w     = (const float*)d_in[11];
    const float* lin2_b     = (const float*)d_in[12];
    const float* n1_g       = (const float*)d_in[13];
    const float* n1_b       = (const float*)d_in[14];
    const float* n2_g       = (const float*)d_in[15];
    const float* n2_b       = (const float*)d_in[16];
    float* out = (float*)d_out;

    float *x, *qkv, *sc, *w, *dbias, *attn, *ff1, *part, *stats;
    cudaGetSymbolAddress((void**)&x,     g_x);
    cudaGetSymbolAddress((void**)&qkv,   g_qkv);
    cudaGetSymbolAddress((void**)&sc,    g_scores);
    cudaGetSymbolAddress((void**)&w,     g_w);
    cudaGetSymbolAddress((void**)&dbias, g_dbias);
    cudaGetSymbolAddress((void**)&attn,  g_attn);
    cudaGetSymbolAddress((void**)&ff1,   g_ff1);
    cudaGetSymbolAddress((void**)&part,  g_part);
    cudaGetSymbolAddress((void**)&stats, g_stats);

    cudaFuncSetAttribute(gemm_mma<true,false>,  cudaFuncAttributeMaxDynamicSharedMemorySize, GEMM_SMEM);
    cudaFuncSetAttribute(gemm_mma<true,true>,   cudaFuncAttributeMaxDynamicSharedMemorySize, GEMM_SMEM);
    cudaFuncSetAttribute(gemm_mma<false,false>, cudaFuncAttributeMaxDynamicSharedMemorySize, GEMM_SMEM);

    dim3 blk(256);
    const long long SE  = (long long)SS * EE;       // 524288
    const long long SQ  = (long long)SS * 1024;     // qkv per-batch stride
    const long long SS2 = (long long)SS * SS;       // 1048576

    // 1) input projection: [8192,128] @ [512,128]^T -> g_x
    gemm_mma<true,false><<<dim3(EE/128, ROWS/128, 1), blk, GEMM_SMEM>>>(
        src, proj_w, proj_b, x, IN_F, IN_F, IN_F, EE,
        1, 0, 0, 0, 0, 0, 1.f);

    // 2) BatchNorm (batch stats) + PE
    bn_part_k<<<64, 512>>>(x, part);
    bn_final_k<<<2, 256>>>(part, stats);
    bn_apply_pe_k<<<(ROWS*EE)/256, 256>>>(x, stats, bn_g, bn_b);

    // 3) distance bias (shared across layers)
    dist_bias_k<<<BB*SS, 256>>>(distances, dist_scale, dbias);

    // 4) layers (shared parameters)
    for (int l = 0; l < NL; l++) {
        // qk = x @ in_proj_w[0:1024]^T  (V third is unused by the reference)
        gemm_mma<true,false><<<dim3(1024/128, ROWS/128, 1), blk, GEMM_SMEM>>>(
            x, in_proj_w, in_proj_b, qkv, EE, EE, EE, 1024,
            1, 0, 0, 0, 0, 0, 1.f);

        // scores[b,h] = (Q_bh @ K_bh^T) * 1/sqrt(HD); batch z=(b*H+h)
        gemm_mma<true,false><<<dim3(SS/128, SS/128, BB*HH), blk, GEMM_SMEM>>>(
            qkv, qkv + EE, nullptr, sc, HD, 1024, 1024, SS,
            HH, SQ, HD, SQ, HD, SS2, 0.125f);

        // per-row: softmax each head, head-average, * dist_bias, renormalize
        attn_w_k<<<BB*SS, 256>>>(sc, dbias, w);

        // attn_out = w @ x (NN), batched over b
        gemm_mma<false,false><<<dim3(EE/128, SS/128, BB), blk, GEMM_SMEM>>>(
            w, x, nullptr, attn, SS, SS, EE, EE,
            1, SS2, 0, SE, 0, SE, 1.f);

        // x = LN(x + attn_out)
        add_ln_k<<<ROWS, 256>>>(x, attn, n1_g, n1_b, x);

        // FFN
        gemm_mma<true,true><<<dim3(FF_DIM/128, ROWS/128, 1), blk, GEMM_SMEM>>>(
            x, lin1_w, lin1_b, ff1, EE, EE, EE, FF_DIM,
            1, 0, 0, 0, 0, 0, 1.f);
        gemm_mma<true,false><<<dim3(EE/128, ROWS/128, 1), blk, GEMM_SMEM>>>(
            ff1, lin2_w, lin2_b, attn, FF_DIM, FF_DIM, FF_DIM, EE,
            1, 0, 0, 0, 0, 0, 1.f);

        // x = LN(x + ff); last layer writes straight to d_out
        add_ln_k<<<ROWS, 256>>>(x, attn, n2_g, n2_b, (l == NL - 1) ? out : x);
    }
}

// round 5
// speedup vs baseline: 3.1462x; 1.5196x over previous
#include <cuda_runtime.h>
#include <cuda_fp16.h>
#include <cstdint>

// Problem constants
#define BB 8
#define SS 1024
#define IN_F 128
#define EE 512
#define HH 8
#define HD 64
#define FF_DIM 2048
#define NL 4
#define ROWS (BB*SS)          // 8192
#define EPS 1e-5f

// ---------------- scratch (device globals; no allocations allowed) ----------
__device__ __align__(16) float g_x[ROWS*EE];                   // 16 MB fp32 (residual stream)
__device__ __align__(16) float g_scores[(size_t)BB*HH*SS*SS];  // 256 MB
__device__ __align__(16) float g_dbias[(size_t)BB*SS*SS];      // 32 MB
__device__ __align__(16) float g_attn[ROWS*EE];                // 16 MB
__device__ __align__(16) float g_part[2*64*EE];
__device__ __align__(16) float g_stats[2*EE];
// split (hi/lo fp16) operand buffers
__device__ __align__(16) __half g_srch[ROWS*IN_F],  g_srcl[ROWS*IN_F];
__device__ __align__(16) __half g_xh[ROWS*EE],      g_xl[ROWS*EE];
__device__ __align__(16) __half g_qkh[ROWS*1024],   g_qkl[ROWS*1024];
__device__ __align__(16) __half g_wh[(size_t)BB*SS*SS], g_wl[(size_t)BB*SS*SS];
__device__ __align__(16) __half g_ffh[ROWS*FF_DIM], g_ffl[ROWS*FF_DIM];
__device__ __align__(16) __half g_pwh[EE*IN_F],     g_pwl[EE*IN_F];
__device__ __align__(16) __half g_iph[1024*EE],     g_ipl[1024*EE];
__device__ __align__(16) __half g_l1h[FF_DIM*EE],   g_l1l[FF_DIM*EE];
__device__ __align__(16) __half g_l2h[EE*FF_DIM],   g_l2l[EE*FF_DIM];

// ====================== helpers =============================================
__device__ __forceinline__ uint32_t smem_u32(const void* p){
    uint32_t a;
    asm("{ .reg .u64 t; cvta.to.shared.u64 t, %1; cvt.u32.u64 %0, t; }"
        : "=r"(a) : "l"(p));
    return a;
}
__device__ __forceinline__ void ldsm4(uint32_t& r0, uint32_t& r1, uint32_t& r2, uint32_t& r3,
                                      uint32_t addr){
    asm volatile("ldmatrix.sync.aligned.m8n8.x4.shared.b16 {%0,%1,%2,%3}, [%4];"
                 : "=r"(r0), "=r"(r1), "=r"(r2), "=r"(r3) : "r"(addr));
}
__device__ __forceinline__ void ldsm4t(uint32_t& r0, uint32_t& r1, uint32_t& r2, uint32_t& r3,
                                       uint32_t addr){
    asm volatile("ldmatrix.sync.aligned.m8n8.x4.trans.shared.b16 {%0,%1,%2,%3}, [%4];"
                 : "=r"(r0), "=r"(r1), "=r"(r2), "=r"(r3) : "r"(addr));
}
__device__ __forceinline__ void mma16816(float* c, const uint32_t* a, const uint32_t* b){
    asm volatile("mma.sync.aligned.m16n8k16.row.col.f32.f16.f16.f32 "
                 "{%0,%1,%2,%3}, {%4,%5,%6,%7}, {%8,%9}, {%0,%1,%2,%3};"
                 : "+f"(c[0]), "+f"(c[1]), "+f"(c[2]), "+f"(c[3])
                 : "r"(a[0]), "r"(a[1]), "r"(a[2]), "r"(a[3]), "r"(b[0]), "r"(b[1]));
}
#define CP16(d,s)   asm volatile("cp.async.cg.shared.global [%0], [%1], 16;" :: "r"(d), "l"(s) : "memory")
#define CPCOMMIT()  asm volatile("cp.async.commit_group;" ::: "memory")
#define CPWAIT1()   asm volatile("cp.async.wait_group 1;" ::: "memory")

// block reductions (256 threads)
__device__ __forceinline__ float brsum(float v, float* red, int tid){
    #pragma unroll
    for (int o = 16; o; o >>= 1) v += __shfl_xor_sync(0xffffffffu, v, o);
    if ((tid & 31) == 0) red[tid >> 5] = v;
    __syncthreads();
    if (tid < 32) {
        float x = (tid < 8) ? red[tid] : 0.f;
        #pragma unroll
        for (int o = 4; o; o >>= 1) x += __shfl_xor_sync(0xffffffffu, x, o);
        if (tid == 0) red[0] = x;
    }
    __syncthreads();
    v = red[0];
    __syncthreads();
    return v;
}
__device__ __forceinline__ float brmax(float v, float* red, int tid){
    #pragma unroll
    for (int o = 16; o; o >>= 1) v = fmaxf(v, __shfl_xor_sync(0xffffffffu, v, o));
    if ((tid & 31) == 0) red[tid >> 5] = v;
    __syncthreads();
    if (tid < 32) {
        float x = (tid < 8) ? red[tid] : -1e30f;
        #pragma unroll
        for (int o = 4; o; o >>= 1) x = fmaxf(x, __shfl_xor_sync(0xffffffffu, x, o));
        if (tid == 0) red[0] = x;
    }
    __syncthreads();
    v = red[0];
    __syncthreads();
    return v;
}

// ====================== fp16x3 mma.sync GEMM (pre-split operands) ===========
// C = alpha * A*B (+bias) (+relu). A: [M,K] row-major split (Ah,Al).
// BTRANS=false: B [N,K] row-major split (NT, plain ldmatrix).
// BTRANS=true : B [K,N] row-major split (NN, ldmatrix.trans).
// OUT: 0 = fp32 C;  1 = split (Ch,Cl) fp16 pair.
// Batch z: A += (z/hdiv)*sA0 + (z%hdiv)*sA1; B likewise; C += z*sC.
// CTA tile 128x128, BK=32, 3-stage cp.async pipeline, 8 warps (64x32 warp tile).
#define GEMM_SMEM (3*32768)

template<bool BTRANS, int OUT, bool RELU>
__global__ __launch_bounds__(256,2) void gemm_mma(
    const __half* __restrict__ Ah_, const __half* __restrict__ Al_,
    const __half* __restrict__ Bh_, const __half* __restrict__ Bl_,
    const float* __restrict__ bias,
    float* __restrict__ Cf, __half* __restrict__ Ch, __half* __restrict__ Cl,
    int K, int lda, int ldb, int ldc,
    int hdiv, long long sA0, long long sA1, long long sB0, long long sB1,
    long long sC, float alpha)
{
    extern __shared__ char sm[];
    int tid = threadIdx.x, lane = tid & 31, wid = tid >> 5;
    int z = blockIdx.z;
    long long aoff = (long long)(z / hdiv) * sA0 + (long long)(z % hdiv) * sA1;
    long long boff = (long long)(z / hdiv) * sB0 + (long long)(z % hdiv) * sB1;
    const __half* Ah = Ah_ + aoff;
    const __half* Al = Al_ + aoff;
    const __half* Bh = Bh_ + boff;
    const __half* Bl = Bl_ + boff;
    int m0 = blockIdx.y * 128, n0 = blockIdx.x * 128;
    int wm0 = (wid >> 2) * 64, wn0 = (wid & 3) * 32;

    float acc[4][4][4];
    #pragma unroll
    for (int i = 0; i < 4; i++)
        #pragma unroll
        for (int j = 0; j < 4; j++)
            #pragma unroll
            for (int e = 0; e < 4; e++) acc[i][j][e] = 0.f;

    uint32_t smBase = smem_u32(sm);
    int nch = K >> 5;

    // stage chunk c into stage-slot s
    auto stage = [&](int c, int s){
        uint32_t bs = smBase + s * 32768;
        int k0 = c * 32;
        #pragma unroll
        for (int j = 0; j < 2; j++) {
            int id = tid + j * 256;
            int r = id >> 2, cc = id & 3;
            uint32_t d = bs + (uint32_t)(r * 64 + ((cc ^ ((r >> 1) & 3)) << 4));
            const __half* pa = Ah + (long long)(m0 + r) * lda + k0 + cc * 8;
            const __half* pl = Al + (long long)(m0 + r) * lda + k0 + cc * 8;
            CP16(d, pa);
            CP16(d + 8192, pl);
        }
        if (!BTRANS) {
            #pragma unroll
            for (int j = 0; j < 2; j++) {
                int id = tid + j * 256;
                int r = id >> 2, cc = id & 3;
                uint32_t d = bs + 16384 + (uint32_t)(r * 64 + ((cc ^ ((r >> 1) & 3)) << 4));
                const __half* pb = Bh + (long long)(n0 + r) * ldb + k0 + cc * 8;
                const __half* pl = Bl + (long long)(n0 + r) * ldb + k0 + cc * 8;
                CP16(d, pb);
                CP16(d + 8192, pl);
            }
        } else {
            #pragma unroll
            for (int j = 0; j < 2; j++) {
                int id = tid + j * 256;
                int k = id >> 4, cc = id & 15;
                uint32_t d = bs + 16384 + (uint32_t)(k * 256 + ((cc ^ (k & 7)) << 4));
                const __half* pb = Bh + (long long)(k0 + k) * ldb + n0 + cc * 8;
                const __half* pl = Bl + (long long)(k0 + k) * ldb + n0 + cc * 8;
                CP16(d, pb);
                CP16(d + 8192, pl);
            }
        }
        CPCOMMIT();
    };

    stage(0, 0);
    if (nch > 1) stage(1, 1); else CPCOMMIT();

    // per-lane ldmatrix address components
    uint32_t aRowB = (uint32_t)(wm0 + (lane & 15)) * 64;
    uint32_t aXor  = ((uint32_t)(lane & 15) >> 1) & 3;
    uint32_t aG    = (uint32_t)(lane >> 4);
    // NT B
    uint32_t bRowB = (uint32_t)(wn0 + ((lane >> 4) << 3) + (lane & 7)) * 64;
    uint32_t bXor  = (((uint32_t)lane & 7) >> 1) & 3;
    uint32_t bG    = (uint32_t)((lane >> 3) & 1);
    // NN (trans) B: smem [32 k rows][128 n] pitch 256B, chunk swizzle c^(k&7)
    uint32_t btRow = ((((uint32_t)lane >> 3) & 1) * 8 + ((uint32_t)lane & 7)) * 256;
    uint32_t btNc  = ((uint32_t)wn0 >> 3) + ((uint32_t)lane >> 4);
    uint32_t btXk  = (uint32_t)lane & 7;

    for (int c = 0; c < nch; c++) {
        CPWAIT1();
        __syncthreads();
        uint32_t base = smBase + (uint32_t)((c % 3) * 32768);
        #pragma unroll
        for (int ks = 0; ks < 2; ks++) {
            uint32_t bh[8], bl[8];
            if (!BTRANS) {
                #pragma unroll
                for (int ntp = 0; ntp < 2; ntp++) {
                    uint32_t ga = (uint32_t)(ks * 2) + bG;
                    uint32_t off = bRowB + (uint32_t)(ntp * 1024) + ((ga ^ bXor) << 4);
                    ldsm4(bh[ntp*4+0], bh[ntp*4+1], bh[ntp*4+2], bh[ntp*4+3], base + 16384 + off);
                    ldsm4(bl[ntp*4+0], bl[ntp*4+1], bl[ntp*4+2], bl[ntp*4+3], base + 24576 + off);
                }
            } else {
                #pragma unroll
                for (int ntp = 0; ntp < 2; ntp++) {
                    uint32_t off = btRow + (uint32_t)(ks * 4096)
                                 + (((btNc + (uint32_t)(ntp * 2)) ^ btXk) << 4);
                    ldsm4t(bh[ntp*4+0], bh[ntp*4+1], bh[ntp*4+2], bh[ntp*4+3], base + 16384 + off);
                    ldsm4t(bl[ntp*4+0], bl[ntp*4+1], bl[ntp*4+2], bl[ntp*4+3], base + 24576 + off);
                }
            }
            #pragma unroll
            for (int mt = 0; mt < 4; mt++) {
                uint32_t ga = (uint32_t)(ks * 2) + aG;
                uint32_t off = aRowB + (uint32_t)(mt * 1024) + ((ga ^ aXor) << 4);
                uint32_t ah[4], al[4];
                ldsm4(ah[0], ah[1], ah[2], ah[3], base + off);
                ldsm4(al[0], al[1], al[2], al[3], base + 8192 + off);
                #pragma unroll
                for (int nt = 0; nt < 4; nt++) {
                    const uint32_t* ph = &bh[(nt >> 1) * 4 + (nt & 1) * 2];
                    const uint32_t* pl = &bl[(nt >> 1) * 4 + (nt & 1) * 2];
                    mma16816(acc[mt][nt], ah, ph);
                    mma16816(acc[mt][nt], ah, pl);
                    mma16816(acc[mt][nt], al, ph);
                }
            }
        }
        if (c + 2 < nch) stage(c + 2, (c + 2) % 3); else CPCOMMIT();
    }

    // ---- epilogue ----
    #pragma unroll
    for (int nt = 0; nt < 4; nt++) {
        int cc = n0 + wn0 + nt * 8 + (lane & 3) * 2;
        float b0 = 0.f, b1 = 0.f;
        if (bias) { b0 = bias[cc]; b1 = bias[cc + 1]; }
        #pragma unroll
        for (int mt = 0; mt < 4; mt++) {
            int r = m0 + wm0 + mt * 16 + (lane >> 2);
            float v0 = acc[mt][nt][0] * alpha + b0;
            float v1 = acc[mt][nt][1] * alpha + b1;
            float v2 = acc[mt][nt][2] * alpha + b0;
            float v3 = acc[mt][nt][3] * alpha + b1;
            if (RELU) { v0 = fmaxf(v0,0.f); v1 = fmaxf(v1,0.f); v2 = fmaxf(v2,0.f); v3 = fmaxf(v3,0.f); }
            if (OUT == 0) {
                float* p = Cf + (long long)z * sC;
                *(float2*)(p + (long long)r * ldc + cc)       = make_float2(v0, v1);
                *(float2*)(p + (long long)(r + 8) * ldc + cc) = make_float2(v2, v3);
            } else {
                __half h0 = __float2half_rn(v0), h1 = __float2half_rn(v1);
                __half h2 = __float2half_rn(v2), h3 = __float2half_rn(v3);
                __half l0 = __float2half_rn(v0 - __half2float(h0));
                __half l1 = __float2half_rn(v1 - __half2float(h1));
                __half l2 = __float2half_rn(v2 - __half2float(h2));
                __half l3 = __float2half_rn(v3 - __half2float(h3));
                __half* ph = Ch + (long long)z * sC;
                __half* pl = Cl + (long long)z * sC;
                *(__half2*)(ph + (long long)r * ldc + cc)       = __halves2half2(h0, h1);
                *(__half2*)(ph + (long long)(r + 8) * ldc + cc) = __halves2half2(h2, h3);
                *(__half2*)(pl + (long long)r * ldc + cc)       = __halves2half2(l0, l1);
                *(__half2*)(pl + (long long)(r + 8) * ldc + cc) = __halves2half2(l2, l3);
            }
        }
    }
}

// ---------------- fp32 -> fp16 hi/lo splitter --------------------------------
__global__ void split_k(const float* __restrict__ in, __half* __restrict__ h,
                        __half* __restrict__ l, int n) {
    int i = blockIdx.x * 256 + threadIdx.x;
    if (i < n) {
        float v = in[i];
        __half hv = __float2half_rn(v);
        h[i] = hv;
        l[i] = __float2half_rn(v - __half2float(hv));
    }
}

// ---------------- BatchNorm (training-mode batch stats), deterministic -----
__global__ void bn_part_k(const float* __restrict__ x, float* __restrict__ part) {
    int e = threadIdx.x;
    int blk = blockIdx.x;
    float s = 0.f, sq = 0.f;
    int r0 = blk * 128;
    for (int r = r0; r < r0 + 128; r++) {
        float v = x[(long long)r * EE + e];
        s += v; sq += v * v;
    }
    part[blk * EE + e] = s;
    part[(64 + blk) * EE + e] = sq;
}

__global__ void bn_final_k(const float* __restrict__ part, float* __restrict__ stats) {
    int e = blockIdx.x * blockDim.x + threadIdx.x;
    float s = 0.f, sq = 0.f;
    for (int i = 0; i < 64; i++) {
        s  += part[i * EE + e];
        sq += part[(64 + i) * EE + e];
    }
    float mu = s / (float)ROWS;
    stats[e] = mu;
    stats[EE + e] = sq / (float)ROWS - mu * mu;
}

// BN apply + PE; also emits split fp16 pair
__global__ void bn_apply_pe_k(float* __restrict__ x, const float* __restrict__ stats,
                              const float* __restrict__ g, const float* __restrict__ b,
                              __half* __restrict__ xh, __half* __restrict__ xl) {
    long long idx = (long long)blockIdx.x * blockDim.x + threadIdx.x;
    int e = (int)(idx & (EE - 1));
    long long r = idx >> 9;
    int s = (int)(r & (SS - 1));
    float mu = stats[e], var = stats[EE + e];
    int j = e >> 1;
    float dt = expf((float)(2 * j) * (-9.210340371976184f / (float)EE));
    float ang = (float)s * dt;
    float pe = (e & 1) ? cosf(ang) : sinf(ang);
    float v = (x[idx] - mu) * rsqrtf(var + EPS) * g[e] + b[e] + pe;
    x[idx] = v;
    __half hv = __float2half_rn(v);
    xh[idx] = hv;
    xl[idx] = __float2half_rn(v - __half2float(hv));
}

// ---------------- distance bias ---------------------------------------------
__global__ void dist_bias_k(const float* __restrict__ d, const float* __restrict__ scale_p,
                            float* __restrict__ bias) {
    int bq = blockIdx.x;
    int tid = threadIdx.x;
    __shared__ float red[8];
    float4 v = *(const float4*)(d + (long long)bq * SS + tid * 4);
    float mx = brmax(fmaxf(fmaxf(v.x, v.y), fmaxf(v.z, v.w)), red, tid);
    float inv_dmax = 1.f / mx;
    float sc = scale_p[0];
    float4 o;
    o.x = expf(sc * (1.f - v.x * inv_dmax));
    o.y = expf(sc * (1.f - v.y * inv_dmax));
    o.z = expf(sc * (1.f - v.z * inv_dmax));
    o.w = expf(sc * (1.f - v.w * inv_dmax));
    *(float4*)(bias + (long long)bq * SS + tid * 4) = o;
}

// ---------------- softmax per head, head-avg, * dist_bias, renorm, split ---
__global__ void attn_w_k(const float* __restrict__ scores, const float* __restrict__ dbias,
                         __half* __restrict__ wh, __half* __restrict__ wl) {
    int bq = blockIdx.x;
    int b = bq >> 10, q = bq & (SS - 1);
    int tid = threadIdx.x;
    __shared__ float red[8];
    float w0 = 0.f, w1 = 0.f, w2 = 0.f, w3 = 0.f;
    const float* sp = scores + ((long long)b * HH * SS + q) * SS + tid * 4;
    #pragma unroll 1
    for (int h = 0; h < HH; h++) {
        float4 v = *(const float4*)(sp + (long long)h * SS * SS);
        float mx = brmax(fmaxf(fmaxf(v.x, v.y), fmaxf(v.z, v.w)), red, tid);
        float e0 = __expf(v.x - mx), e1 = __expf(v.y - mx);
        float e2 = __expf(v.z - mx), e3 = __expf(v.w - mx);
        float s = brsum(e0 + e1 + e2 + e3, red, tid);
        float inv = 1.f / s;
        w0 += e0 * inv; w1 += e1 * inv; w2 += e2 * inv; w3 += e3 * inv;
    }
    float4 db = *(const float4*)(dbias + (long long)bq * SS + tid * 4);
    w0 *= db.x; w1 *= db.y; w2 *= db.z; w3 *= db.w;
    float s = brsum(w0 + w1 + w2 + w3, red, tid);
    float inv = 1.f / s;
    w0 *= inv; w1 *= inv; w2 *= inv; w3 *= inv;
    __half h0 = __float2half_rn(w0), h1 = __float2half_rn(w1);
    __half h2 = __float2half_rn(w2), h3 = __float2half_rn(w3);
    long long o = (long long)bq * SS + tid * 4;
    *(__half2*)(wh + o)     = __halves2half2(h0, h1);
    *(__half2*)(wh + o + 2) = __halves2half2(h2, h3);
    *(__half2*)(wl + o)     = __halves2half2(__float2half_rn(w0 - __half2float(h0)),
                                             __float2half_rn(w1 - __half2float(h1)));
    *(__half2*)(wl + o + 2) = __halves2half2(__float2half_rn(w2 - __half2float(h2)),
                                             __float2half_rn(w3 - __half2float(h3)));
}

// ---------------- fused residual + LayerNorm (+optional split) --------------
template<bool SPLIT>
__global__ void add_ln_k(const float* __restrict__ x, const float* __restrict__ r,
                         const float* __restrict__ g, const float* __restrict__ b,
                         float* __restrict__ out, __half* __restrict__ oh,
                         __half* __restrict__ ol) {
    int row = blockIdx.x;
    int tid = threadIdx.x;
    __shared__ float red[8];
    long long base = (long long)row * EE;
    float2 v = *(const float2*)(x + base + tid * 2);
    float2 rr = *(const float2*)(r + base + tid * 2);
    v.x += rr.x; v.y += rr.y;
    float mean = brsum(v.x + v.y, red, tid) * (1.f / (float)EE);
    float var = brsum(v.x * v.x + v.y * v.y, red, tid) * (1.f / (float)EE) - mean * mean;
    float inv = rsqrtf(var + EPS);
    float2 gg = *(const float2*)(g + tid * 2);
    float2 bb = *(const float2*)(b + tid * 2);
    float o0 = (v.x - mean) * inv * gg.x + bb.x;
    float o1 = (v.y - mean) * inv * gg.y + bb.y;
    *(float2*)(out + base + tid * 2) = make_float2(o0, o1);
    if (SPLIT) {
        __half h0 = __float2half_rn(o0), h1 = __float2half_rn(o1);
        *(__half2*)(oh + base + tid * 2) = __halves2half2(h0, h1);
        *(__half2*)(ol + base + tid * 2) =
            __halves2half2(__float2half_rn(o0 - __half2float(h0)),
                           __float2half_rn(o1 - __half2float(h1)));
    }
}

// ---------------- launch -----------------------------------------------------
extern "C" void kernel_launch(void* const* d_in, const int* in_sizes, int n_in,
                              void* d_out, int out_size) {
    (void)in_sizes; (void)n_in; (void)out_size;
    const float* src        = (const float*)d_in[0];
    const float* distances  = (const float*)d_in[1];
    const float* proj_w     = (const float*)d_in[2];
    const float* proj_b     = (const float*)d_in[3];
    const float* bn_g       = (const float*)d_in[4];
    const float* bn_b       = (const float*)d_in[5];
    const float* in_proj_w  = (const float*)d_in[6];
    const float* in_proj_b  = (const float*)d_in[7];
    const float* dist_scale = (const float*)d_in[8];
    const float* lin1_w     = (const float*)d_in[9];
    const float* lin1_b     = (const float*)d_in[10];
    const float* lin2_w     = (const float*)d_in[11];
    const float* lin2_b     = (const float*)d_in[12];
    const float* n1_g       = (const float*)d_in[13];
    const float* n1_b       = (const float*)d_in[14];
    const float* n2_g       = (const float*)d_in[15];
    const float* n2_b       = (const float*)d_in[16];
    float* out = (float*)d_out;

    float *x, *sc, *dbias, *attn, *part, *stats;
    __half *srch,*srcl,*xh,*xl,*qkh,*qkl,*wh,*wl,*ffh,*ffl;
    __half *pwh,*pwl,*iph,*ipl,*l1h,*l1l,*l2h,*l2l;
    cudaGetSymbolAddress((void**)&x,     g_x);
    cudaGetSymbolAddress((void**)&sc,    g_scores);
    cudaGetSymbolAddress((void**)&dbias, g_dbias);
    cudaGetSymbolAddress((void**)&attn,  g_attn);
    cudaGetSymbolAddress((void**)&part,  g_part);
    cudaGetSymbolAddress((void**)&stats, g_stats);
    cudaGetSymbolAddress((void**)&srch,  g_srch); cudaGetSymbolAddress((void**)&srcl, g_srcl);
    cudaGetSymbolAddress((void**)&xh,    g_xh);   cudaGetSymbolAddress((void**)&xl,   g_xl);
    cudaGetSymbolAddress((void**)&qkh,   g_qkh);  cudaGetSymbolAddress((void**)&qkl,  g_qkl);
    cudaGetSymbolAddress((void**)&wh,    g_wh);   cudaGetSymbolAddress((void**)&wl,   g_wl);
    cudaGetSymbolAddress((void**)&ffh,   g_ffh);  cudaGetSymbolAddress((void**)&ffl,  g_ffl);
    cudaGetSymbolAddress((void**)&pwh,   g_pwh);  cudaGetSymbolAddress((void**)&pwl,  g_pwl);
    cudaGetSymbolAddress((void**)&iph,   g_iph);  cudaGetSymbolAddress((void**)&ipl,  g_ipl);
    cudaGetSymbolAddress((void**)&l1h,   g_l1h);  cudaGetSymbolAddress((void**)&l1l,  g_l1l);
    cudaGetSymbolAddress((void**)&l2h,   g_l2h);  cudaGetSymbolAddress((void**)&l2l,  g_l2l);

    cudaFuncSetAttribute(gemm_mma<false,0,false>, cudaFuncAttributeMaxDynamicSharedMemorySize, GEMM_SMEM);
    cudaFuncSetAttribute(gemm_mma<false,1,false>, cudaFuncAttributeMaxDynamicSharedMemorySize, GEMM_SMEM);
    cudaFuncSetAttribute(gemm_mma<false,1,true>,  cudaFuncAttributeMaxDynamicSharedMemorySize, GEMM_SMEM);
    cudaFuncSetAttribute(gemm_mma<true,0,false>,  cudaFuncAttributeMaxDynamicSharedMemorySize, GEMM_SMEM);

    dim3 blk(256);
    const long long SE  = (long long)SS * EE;
    const long long SQ  = (long long)SS * 1024;
    const long long SS2 = (long long)SS * SS;

    // 0) one-time splits (inputs + weights)
    split_k<<<(ROWS*IN_F+255)/256, 256>>>(src, srch, srcl, ROWS*IN_F);
    split_k<<<(EE*IN_F+255)/256, 256>>>(proj_w, pwh, pwl, EE*IN_F);
    split_k<<<(1024*EE+255)/256, 256>>>(in_proj_w, iph, ipl, 1024*EE);  // q,k rows only
    split_k<<<(FF_DIM*EE+255)/256, 256>>>(lin1_w, l1h, l1l, FF_DIM*EE);
    split_k<<<(EE*FF_DIM+255)/256, 256>>>(lin2_w, l2h, l2l, EE*FF_DIM);

    // 1) input projection -> g_x (fp32)
    gemm_mma<false,0,false><<<dim3(EE/128, ROWS/128, 1), blk, GEMM_SMEM>>>(
        srch, srcl, pwh, pwl, proj_b, x, nullptr, nullptr,
        IN_F, IN_F, IN_F, EE, 1, 0, 0, 0, 0, 0, 1.f);

    // 2) BatchNorm (batch stats) + PE (+split)
    bn_part_k<<<64, 512>>>(x, part);
    bn_final_k<<<2, 256>>>(part, stats);
    bn_apply_pe_k<<<(ROWS*EE)/256, 256>>>(x, stats, bn_g, bn_b, xh, xl);

    // 3) distance bias (shared across layers)
    dist_bias_k<<<BB*SS, 256>>>(distances, dist_scale, dbias);

    // 4) layers (shared parameters)
    for (int l = 0; l < NL; l++) {
        // qk = x @ in_proj_w[0:1024]^T + b   -> split qkh/qkl directly
        gemm_mma<false,1,false><<<dim3(1024/128, ROWS/128, 1), blk, GEMM_SMEM>>>(
            xh, xl, iph, ipl, in_proj_b, nullptr, qkh, qkl,
            EE, EE, EE, 1024, 1, 0, 0, 0, 0, 0, 1.f);

        // scores[b,h] = (Q_bh @ K_bh^T) * 1/sqrt(HD)
        gemm_mma<false,0,false><<<dim3(SS/128, SS/128, BB*HH), blk, GEMM_SMEM>>>(
            qkh, qkl, qkh + EE, qkl + EE, nullptr, sc, nullptr, nullptr,
            HD, 1024, 1024, SS, HH, SQ, HD, SQ, HD, SS2, 0.125f);

        // softmax/head-avg/dist-bias/renorm -> split w
        attn_w_k<<<BB*SS, 256>>>(sc, dbias, wh, wl);

        // attn_out = w @ x  (NN: B=[K][N] row-major x, ldmatrix.trans)
        gemm_mma<true,0,false><<<dim3(EE/128, SS/128, BB), blk, GEMM_SMEM>>>(
            wh, wl, xh, xl, nullptr, attn, nullptr, nullptr,
            SS, SS, EE, EE, 1, SS2, 0, SE, 0, SE, 1.f);

        // x = LN(x + attn_out) (+split)
        add_ln_k<true><<<ROWS, 256>>>(x, attn, n1_g, n1_b, x, xh, xl);

        // FFN: ff1 relu -> split only; ff2 -> fp32
        gemm_mma<false,1,true><<<dim3(FF_DIM/128, ROWS/128, 1), blk, GEMM_SMEM>>>(
            xh, xl, l1h, l1l, lin1_b, nullptr, ffh, ffl,
            EE, EE, EE, FF_DIM, 1, 0, 0, 0, 0, 0, 1.f);
        gemm_mma<false,0,false><<<dim3(EE/128, ROWS/128, 1), blk, GEMM_SMEM>>>(
            ffh, ffl, l2h, l2l, lin2_b, attn, nullptr, nullptr,
            FF_DIM, FF_DIM, FF_DIM, EE, 1, 0, 0, 0, 0, 0, 1.f);

        // x = LN(x + ff); last layer -> d_out (no split needed)
        if (l == NL - 1)
            add_ln_k<false><<<ROWS, 256>>>(x, attn, n2_g, n2_b, out, nullptr, nullptr);
        else
            add_ln_k<true><<<ROWS, 256>>>(x, attn, n2_g, n2_b, x, xh, xl);
    }
}

// round 6
// speedup vs baseline: 3.5572x; 1.1306x over previous
#include <cuda_runtime.h>
#include <cuda_fp16.h>
#include <cstdint>

// Problem constants
#define BB 8
#define SS 1024
#define IN_F 128
#define EE 512
#define HH 8
#define HD 64
#define FF_DIM 2048
#define NL 4
#define ROWS (BB*SS)          // 8192
#define EPS 1e-5f

// ---------------- scratch (device globals; no allocations allowed) ----------
__device__ __align__(16) float g_x[ROWS*EE];                   // fp32 residual stream
__device__ __align__(16) float g_scores[(size_t)BB*HH*SS*SS];  // 256 MB
__device__ __align__(16) float g_dbias[(size_t)BB*SS*SS];      // 32 MB
__device__ __align__(16) float g_attn[ROWS*EE];                // 16 MB
__device__ __align__(16) float g_part[2*64*EE];
__device__ __align__(16) float g_stats[2*EE];
// split (hi/lo fp16) operand buffers
__device__ __align__(16) __half g_srch[ROWS*IN_F],  g_srcl[ROWS*IN_F];
__device__ __align__(16) __half g_xh[ROWS*EE],      g_xl[ROWS*EE];
__device__ __align__(16) __half g_qkh[ROWS*1024],   g_qkl[ROWS*1024];
__device__ __align__(16) __half g_wh[(size_t)BB*SS*SS];        // single fp16 attn weights
__device__ __align__(16) __half g_ffh[ROWS*FF_DIM];            // single fp16 relu acts
__device__ __align__(16) __half g_pwh[EE*IN_F],     g_pwl[EE*IN_F];
__device__ __align__(16) __half g_iph[1024*EE],     g_ipl[1024*EE];
__device__ __align__(16) __half g_l1h[FF_DIM*EE],   g_l1l[FF_DIM*EE];
__device__ __align__(16) __half g_l2h[EE*FF_DIM],   g_l2l[EE*FF_DIM];

// ====================== helpers =============================================
__device__ __forceinline__ uint32_t smem_u32(const void* p){
    uint32_t a;
    asm("{ .reg .u64 t; cvta.to.shared.u64 t, %1; cvt.u32.u64 %0, t; }"
        : "=r"(a) : "l"(p));
    return a;
}
__device__ __forceinline__ void ldsm4(uint32_t& r0, uint32_t& r1, uint32_t& r2, uint32_t& r3,
                                      uint32_t addr){
    asm volatile("ldmatrix.sync.aligned.m8n8.x4.shared.b16 {%0,%1,%2,%3}, [%4];"
                 : "=r"(r0), "=r"(r1), "=r"(r2), "=r"(r3) : "r"(addr));
}
__device__ __forceinline__ void ldsm4t(uint32_t& r0, uint32_t& r1, uint32_t& r2, uint32_t& r3,
                                       uint32_t addr){
    asm volatile("ldmatrix.sync.aligned.m8n8.x4.trans.shared.b16 {%0,%1,%2,%3}, [%4];"
                 : "=r"(r0), "=r"(r1), "=r"(r2), "=r"(r3) : "r"(addr));
}
__device__ __forceinline__ void mma16816(float* c, const uint32_t* a, const uint32_t* b){
    asm volatile("mma.sync.aligned.m16n8k16.row.col.f32.f16.f16.f32 "
                 "{%0,%1,%2,%3}, {%4,%5,%6,%7}, {%8,%9}, {%0,%1,%2,%3};"
                 : "+f"(c[0]), "+f"(c[1]), "+f"(c[2]), "+f"(c[3])
                 : "r"(a[0]), "r"(a[1]), "r"(a[2]), "r"(a[3]), "r"(b[0]), "r"(b[1]));
}
#define CP16(d,s)   asm volatile("cp.async.cg.shared.global [%0], [%1], 16;" :: "r"(d), "l"(s) : "memory")
#define CPCOMMIT()  asm volatile("cp.async.commit_group;" ::: "memory")
#define CPWAIT1()   asm volatile("cp.async.wait_group 1;" ::: "memory")

// block reductions (256 threads)
__device__ __forceinline__ float brsum(float v, float* red, int tid){
    #pragma unroll
    for (int o = 16; o; o >>= 1) v += __shfl_xor_sync(0xffffffffu, v, o);
    if ((tid & 31) == 0) red[tid >> 5] = v;
    __syncthreads();
    if (tid < 32) {
        float x = (tid < 8) ? red[tid] : 0.f;
        #pragma unroll
        for (int o = 4; o; o >>= 1) x += __shfl_xor_sync(0xffffffffu, x, o);
        if (tid == 0) red[0] = x;
    }
    __syncthreads();
    v = red[0];
    __syncthreads();
    return v;
}
__device__ __forceinline__ float brmax(float v, float* red, int tid){
    #pragma unroll
    for (int o = 16; o; o >>= 1) v = fmaxf(v, __shfl_xor_sync(0xffffffffu, v, o));
    if ((tid & 31) == 0) red[tid >> 5] = v;
    __syncthreads();
    if (tid < 32) {
        float x = (tid < 8) ? red[tid] : -1e30f;
        #pragma unroll
        for (int o = 4; o; o >>= 1) x = fmaxf(x, __shfl_xor_sync(0xffffffffu, x, o));
        if (tid == 0) red[0] = x;
    }
    __syncthreads();
    v = red[0];
    __syncthreads();
    return v;
}

// ====================== fp16 multi-pass mma.sync GEMM =======================
// C = alpha * A*B (+bias) (+relu).
// ASPLIT=true : A has hi+lo planes -> 3 MMA passes (AhBh + AhBl + AlBh).
// ASPLIT=false: A is single fp16   -> 2 MMA passes (AhBh + AhBl).
// BTRANS=false: B [N,K] row-major split (NT). BTRANS=true: B [K,N] (NN, trans).
// OUT: 0 fp32, 1 split pair, 2 single fp16.
// Batch z: A += (z/hdiv)*sA0 + (z%hdiv)*sA1; B likewise; C += z*sC.
// CTA tile 128x128, BK=32, 3-stage cp.async pipeline, 8 warps (64x32 warp tile).
#define GEMM_SMEM (3*32768)

template<bool BTRANS, bool ASPLIT, int OUT, bool RELU>
__global__ __launch_bounds__(256,2) void gemm_mma(
    const __half* __restrict__ Ah_, const __half* __restrict__ Al_,
    const __half* __restrict__ Bh_, const __half* __restrict__ Bl_,
    const float* __restrict__ bias,
    float* __restrict__ Cf, __half* __restrict__ Ch, __half* __restrict__ Cl,
    int K, int lda, int ldb, int ldc,
    int hdiv, long long sA0, long long sA1, long long sB0, long long sB1,
    long long sC, float alpha)
{
    extern __shared__ char sm[];
    int tid = threadIdx.x, lane = tid & 31, wid = tid >> 5;
    int z = blockIdx.z;
    long long aoff = (long long)(z / hdiv) * sA0 + (long long)(z % hdiv) * sA1;
    long long boff = (long long)(z / hdiv) * sB0 + (long long)(z % hdiv) * sB1;
    const __half* Ah = Ah_ + aoff;
    const __half* Al = ASPLIT ? (Al_ + aoff) : nullptr;
    const __half* Bh = Bh_ + boff;
    const __half* Bl = Bl_ + boff;
    int m0 = blockIdx.y * 128, n0 = blockIdx.x * 128;
    int wm0 = (wid >> 2) * 64, wn0 = (wid & 3) * 32;

    float acc[4][4][4];
    #pragma unroll
    for (int i = 0; i < 4; i++)
        #pragma unroll
        for (int j = 0; j < 4; j++)
            #pragma unroll
            for (int e = 0; e < 4; e++) acc[i][j][e] = 0.f;

    uint32_t smBase = smem_u32(sm);
    int nch = K >> 5;

    auto stage = [&](int c, int s){
        uint32_t bs = smBase + s * 32768;
        int k0 = c * 32;
        #pragma unroll
        for (int j = 0; j < 2; j++) {
            int id = tid + j * 256;
            int r = id >> 2, cc = id & 3;
            uint32_t d = bs + (uint32_t)(r * 64 + ((cc ^ ((r >> 1) & 3)) << 4));
            CP16(d, Ah + (long long)(m0 + r) * lda + k0 + cc * 8);
            if (ASPLIT) CP16(d + 8192, Al + (long long)(m0 + r) * lda + k0 + cc * 8);
        }
        if (!BTRANS) {
            #pragma unroll
            for (int j = 0; j < 2; j++) {
                int id = tid + j * 256;
                int r = id >> 2, cc = id & 3;
                uint32_t d = bs + 16384 + (uint32_t)(r * 64 + ((cc ^ ((r >> 1) & 3)) << 4));
                CP16(d, Bh + (long long)(n0 + r) * ldb + k0 + cc * 8);
                CP16(d + 8192, Bl + (long long)(n0 + r) * ldb + k0 + cc * 8);
            }
        } else {
            #pragma unroll
            for (int j = 0; j < 2; j++) {
                int id = tid + j * 256;
                int k = id >> 4, cc = id & 15;
                uint32_t d = bs + 16384 + (uint32_t)(k * 256 + ((cc ^ (k & 7)) << 4));
                CP16(d, Bh + (long long)(k0 + k) * ldb + n0 + cc * 8);
                CP16(d + 8192, Bl + (long long)(k0 + k) * ldb + n0 + cc * 8);
            }
        }
        CPCOMMIT();
    };

    stage(0, 0);
    if (nch > 1) stage(1, 1); else CPCOMMIT();

    uint32_t aRowB = (uint32_t)(wm0 + (lane & 15)) * 64;
    uint32_t aXor  = ((uint32_t)(lane & 15) >> 1) & 3;
    uint32_t aG    = (uint32_t)(lane >> 4);
    uint32_t bRowB = (uint32_t)(wn0 + ((lane >> 4) << 3) + (lane & 7)) * 64;
    uint32_t bXor  = (((uint32_t)lane & 7) >> 1) & 3;
    uint32_t bG    = (uint32_t)((lane >> 3) & 1);
    uint32_t btRow = ((((uint32_t)lane >> 3) & 1) * 8 + ((uint32_t)lane & 7)) * 256;
    uint32_t btNc  = ((uint32_t)wn0 >> 3) + ((uint32_t)lane >> 4);
    uint32_t btXk  = (uint32_t)lane & 7;

    for (int c = 0; c < nch; c++) {
        CPWAIT1();
        __syncthreads();
        uint32_t base = smBase + (uint32_t)((c % 3) * 32768);
        #pragma unroll
        for (int ks = 0; ks < 2; ks++) {
            uint32_t bh[8], bl[8];
            if (!BTRANS) {
                #pragma unroll
                for (int ntp = 0; ntp < 2; ntp++) {
                    uint32_t ga = (uint32_t)(ks * 2) + bG;
                    uint32_t off = bRowB + (uint32_t)(ntp * 1024) + ((ga ^ bXor) << 4);
                    ldsm4(bh[ntp*4+0], bh[ntp*4+1], bh[ntp*4+2], bh[ntp*4+3], base + 16384 + off);
                    ldsm4(bl[ntp*4+0], bl[ntp*4+1], bl[ntp*4+2], bl[ntp*4+3], base + 24576 + off);
                }
            } else {
                #pragma unroll
                for (int ntp = 0; ntp < 2; ntp++) {
                    uint32_t off = btRow + (uint32_t)(ks * 4096)
                                 + (((btNc + (uint32_t)(ntp * 2)) ^ btXk) << 4);
                    ldsm4t(bh[ntp*4+0], bh[ntp*4+1], bh[ntp*4+2], bh[ntp*4+3], base + 16384 + off);
                    ldsm4t(bl[ntp*4+0], bl[ntp*4+1], bl[ntp*4+2], bl[ntp*4+3], base + 24576 + off);
                }
            }
            #pragma unroll
            for (int mt = 0; mt < 4; mt++) {
                uint32_t ga = (uint32_t)(ks * 2) + aG;
                uint32_t off = aRowB + (uint32_t)(mt * 1024) + ((ga ^ aXor) << 4);
                uint32_t ah[4], al[4];
                ldsm4(ah[0], ah[1], ah[2], ah[3], base + off);
                if (ASPLIT) ldsm4(al[0], al[1], al[2], al[3], base + 8192 + off);
                #pragma unroll
                for (int nt = 0; nt < 4; nt++) {
                    const uint32_t* ph = &bh[(nt >> 1) * 4 + (nt & 1) * 2];
                    const uint32_t* pl = &bl[(nt >> 1) * 4 + (nt & 1) * 2];
                    mma16816(acc[mt][nt], ah, ph);
                    mma16816(acc[mt][nt], ah, pl);
                    if (ASPLIT) mma16816(acc[mt][nt], al, ph);
                }
            }
        }
        if (c + 2 < nch) stage(c + 2, (c + 2) % 3); else CPCOMMIT();
    }

    // ---- epilogue ----
    #pragma unroll
    for (int nt = 0; nt < 4; nt++) {
        int cc = n0 + wn0 + nt * 8 + (lane & 3) * 2;
        float b0 = 0.f, b1 = 0.f;
        if (bias) { b0 = bias[cc]; b1 = bias[cc + 1]; }
        #pragma unroll
        for (int mt = 0; mt < 4; mt++) {
            int r = m0 + wm0 + mt * 16 + (lane >> 2);
            float v0 = acc[mt][nt][0] * alpha + b0;
            float v1 = acc[mt][nt][1] * alpha + b1;
            float v2 = acc[mt][nt][2] * alpha + b0;
            float v3 = acc[mt][nt][3] * alpha + b1;
            if (RELU) { v0 = fmaxf(v0,0.f); v1 = fmaxf(v1,0.f); v2 = fmaxf(v2,0.f); v3 = fmaxf(v3,0.f); }
            if (OUT == 0) {
                float* p = Cf + (long long)z * sC;
                *(float2*)(p + (long long)r * ldc + cc)       = make_float2(v0, v1);
                *(float2*)(p + (long long)(r + 8) * ldc + cc) = make_float2(v2, v3);
            } else if (OUT == 1) {
                __half h0 = __float2half_rn(v0), h1 = __float2half_rn(v1);
                __half h2 = __float2half_rn(v2), h3 = __float2half_rn(v3);
                __half* ph = Ch + (long long)z * sC;
                __half* pl = Cl + (long long)z * sC;
                *(__half2*)(ph + (long long)r * ldc + cc)       = __halves2half2(h0, h1);
                *(__half2*)(ph + (long long)(r + 8) * ldc + cc) = __halves2half2(h2, h3);
                *(__half2*)(pl + (long long)r * ldc + cc) =
                    __halves2half2(__float2half_rn(v0 - __half2float(h0)),
                                   __float2half_rn(v1 - __half2float(h1)));
                *(__half2*)(pl + (long long)(r + 8) * ldc + cc) =
                    __halves2half2(__float2half_rn(v2 - __half2float(h2)),
                                   __float2half_rn(v3 - __half2float(h3)));
            } else {
                __half* ph = Ch + (long long)z * sC;
                *(__half2*)(ph + (long long)r * ldc + cc) =
                    __halves2half2(__float2half_rn(v0), __float2half_rn(v1));
                *(__half2*)(ph + (long long)(r + 8) * ldc + cc) =
                    __halves2half2(__float2half_rn(v2), __float2half_rn(v3));
            }
        }
    }
}

// ---------------- fp32 -> fp16 hi/lo splitter --------------------------------
__global__ void split_k(const float* __restrict__ in, __half* __restrict__ h,
                        __half* __restrict__ l, int n) {
    int i = blockIdx.x * 256 + threadIdx.x;
    if (i < n) {
        float v = in[i];
        __half hv = __float2half_rn(v);
        h[i] = hv;
        l[i] = __float2half_rn(v - __half2float(hv));
    }
}

// ---------------- BatchNorm (training-mode batch stats), deterministic -----
__global__ void bn_part_k(const float* __restrict__ x, float* __restrict__ part) {
    int e = threadIdx.x;
    int blk = blockIdx.x;
    float s = 0.f, sq = 0.f;
    int r0 = blk * 128;
    for (int r = r0; r < r0 + 128; r++) {
        float v = x[(long long)r * EE + e];
        s += v; sq += v * v;
    }
    part[blk * EE + e] = s;
    part[(64 + blk) * EE + e] = sq;
}

__global__ void bn_final_k(const float* __restrict__ part, float* __restrict__ stats) {
    int e = blockIdx.x * blockDim.x + threadIdx.x;
    float s = 0.f, sq = 0.f;
    for (int i = 0; i < 64; i++) {
        s  += part[i * EE + e];
        sq += part[(64 + i) * EE + e];
    }
    float mu = s / (float)ROWS;
    stats[e] = mu;
    stats[EE + e] = sq / (float)ROWS - mu * mu;
}

__global__ void bn_apply_pe_k(float* __restrict__ x, const float* __restrict__ stats,
                              const float* __restrict__ g, const float* __restrict__ b,
                              __half* __restrict__ xh, __half* __restrict__ xl) {
    long long idx = (long long)blockIdx.x * blockDim.x + threadIdx.x;
    int e = (int)(idx & (EE - 1));
    long long r = idx >> 9;
    int s = (int)(r & (SS - 1));
    float mu = stats[e], var = stats[EE + e];
    int j = e >> 1;
    float dt = expf((float)(2 * j) * (-9.210340371976184f / (float)EE));
    float ang = (float)s * dt;
    float pe = (e & 1) ? cosf(ang) : sinf(ang);
    float v = (x[idx] - mu) * rsqrtf(var + EPS) * g[e] + b[e] + pe;
    x[idx] = v;
    __half hv = __float2half_rn(v);
    xh[idx] = hv;
    xl[idx] = __float2half_rn(v - __half2float(hv));
}

// ---------------- distance bias ---------------------------------------------
__global__ void dist_bias_k(const float* __restrict__ d, const float* __restrict__ scale_p,
                            float* __restrict__ bias) {
    int bq = blockIdx.x;
    int tid = threadIdx.x;
    __shared__ float red[8];
    float4 v = *(const float4*)(d + (long long)bq * SS + tid * 4);
    float mx = brmax(fmaxf(fmaxf(v.x, v.y), fmaxf(v.z, v.w)), red, tid);
    float inv_dmax = 1.f / mx;
    float sc = scale_p[0];
    float4 o;
    o.x = expf(sc * (1.f - v.x * inv_dmax));
    o.y = expf(sc * (1.f - v.y * inv_dmax));
    o.z = expf(sc * (1.f - v.z * inv_dmax));
    o.w = expf(sc * (1.f - v.w * inv_dmax));
    *(float4*)(bias + (long long)bq * SS + tid * 4) = o;
}

// ---------------- softmax per head, head-avg, * dist_bias, renorm ----------
__global__ void attn_w_k(const float* __restrict__ scores, const float* __restrict__ dbias,
                         __half* __restrict__ wh) {
    int bq = blockIdx.x;
    int b = bq >> 10, q = bq & (SS - 1);
    int tid = threadIdx.x;
    __shared__ float red[8];
    float w0 = 0.f, w1 = 0.f, w2 = 0.f, w3 = 0.f;
    const float* sp = scores + ((long long)b * HH * SS + q) * SS + tid * 4;
    #pragma unroll 1
    for (int h = 0; h < HH; h++) {
        float4 v = *(const float4*)(sp + (long long)h * SS * SS);
        float mx = brmax(fmaxf(fmaxf(v.x, v.y), fmaxf(v.z, v.w)), red, tid);
        float e0 = __expf(v.x - mx), e1 = __expf(v.y - mx);
        float e2 = __expf(v.z - mx), e3 = __expf(v.w - mx);
        float s = brsum(e0 + e1 + e2 + e3, red, tid);
        float inv = 1.f / s;
        w0 += e0 * inv; w1 += e1 * inv; w2 += e2 * inv; w3 += e3 * inv;
    }
    float4 db = *(const float4*)(dbias + (long long)bq * SS + tid * 4);
    w0 *= db.x; w1 *= db.y; w2 *= db.z; w3 *= db.w;
    float s = brsum(w0 + w1 + w2 + w3, red, tid);
    float inv = 1.f / s;
    long long o = (long long)bq * SS + tid * 4;
    *(__half2*)(wh + o)     = __halves2half2(__float2half_rn(w0 * inv), __float2half_rn(w1 * inv));
    *(__half2*)(wh + o + 2) = __halves2half2(__float2half_rn(w2 * inv), __float2half_rn(w3 * inv));
}

// ---------------- fused residual + LayerNorm (+optional split) --------------
template<bool SPLIT>
__global__ void add_ln_k(const float* __restrict__ x, const float* __restrict__ r,
                         const float* __restrict__ g, const float* __restrict__ b,
                         float* __restrict__ out, __half* __restrict__ oh,
                         __half* __restrict__ ol) {
    int row = blockIdx.x;
    int tid = threadIdx.x;
    __shared__ float red[8];
    long long base = (long long)row * EE;
    float2 v = *(const float2*)(x + base + tid * 2);
    float2 rr = *(const float2*)(r + base + tid * 2);
    v.x += rr.x; v.y += rr.y;
    float mean = brsum(v.x + v.y, red, tid) * (1.f / (float)EE);
    float var = brsum(v.x * v.x + v.y * v.y, red, tid) * (1.f / (float)EE) - mean * mean;
    float inv = rsqrtf(var + EPS);
    float2 gg = *(const float2*)(g + tid * 2);
    float2 bb = *(const float2*)(b + tid * 2);
    float o0 = (v.x - mean) * inv * gg.x + bb.x;
    float o1 = (v.y - mean) * inv * gg.y + bb.y;
    *(float2*)(out + base + tid * 2) = make_float2(o0, o1);
    if (SPLIT) {
        __half h0 = __float2half_rn(o0), h1 = __float2half_rn(o1);
        *(__half2*)(oh + base + tid * 2) = __halves2half2(h0, h1);
        *(__half2*)(ol + base + tid * 2) =
            __halves2half2(__float2half_rn(o0 - __half2float(h0)),
                           __float2half_rn(o1 - __half2float(h1)));
    }
}

// ---------------- launch -----------------------------------------------------
extern "C" void kernel_launch(void* const* d_in, const int* in_sizes, int n_in,
                              void* d_out, int out_size) {
    (void)in_sizes; (void)n_in; (void)out_size;
    const float* src        = (const float*)d_in[0];
    const float* distances  = (const float*)d_in[1];
    const float* proj_w     = (const float*)d_in[2];
    const float* proj_b     = (const float*)d_in[3];
    const float* bn_g       = (const float*)d_in[4];
    const float* bn_b       = (const float*)d_in[5];
    const float* in_proj_w  = (const float*)d_in[6];
    const float* in_proj_b  = (const float*)d_in[7];
    const float* dist_scale = (const float*)d_in[8];
    const float* lin1_w     = (const float*)d_in[9];
    const float* lin1_b     = (const float*)d_in[10];
    const float* lin2_w     = (const float*)d_in[11];
    const float* lin2_b     = (const float*)d_in[12];
    const float* n1_g       = (const float*)d_in[13];
    const float* n1_b       = (const float*)d_in[14];
    const float* n2_g       = (const float*)d_in[15];
    const float* n2_b       = (const float*)d_in[16];
    float* out = (float*)d_out;

    float *x, *sc, *dbias, *attn, *part, *stats;
    __half *srch,*srcl,*xh,*xl,*qkh,*qkl,*wh,*ffh;
    __half *pwh,*pwl,*iph,*ipl,*l1h,*l1l,*l2h,*l2l;
    cudaGetSymbolAddress((void**)&x,     g_x);
    cudaGetSymbolAddress((void**)&sc,    g_scores);
    cudaGetSymbolAddress((void**)&dbias, g_dbias);
    cudaGetSymbolAddress((void**)&attn,  g_attn);
    cudaGetSymbolAddress((void**)&part,  g_part);
    cudaGetSymbolAddress((void**)&stats, g_stats);
    cudaGetSymbolAddress((void**)&srch,  g_srch); cudaGetSymbolAddress((void**)&srcl, g_srcl);
    cudaGetSymbolAddress((void**)&xh,    g_xh);   cudaGetSymbolAddress((void**)&xl,   g_xl);
    cudaGetSymbolAddress((void**)&qkh,   g_qkh);  cudaGetSymbolAddress((void**)&qkl,  g_qkl);
    cudaGetSymbolAddress((void**)&wh,    g_wh);
    cudaGetSymbolAddress((void**)&ffh,   g_ffh);
    cudaGetSymbolAddress((void**)&pwh,   g_pwh);  cudaGetSymbolAddress((void**)&pwl,  g_pwl);
    cudaGetSymbolAddress((void**)&iph,   g_iph);  cudaGetSymbolAddress((void**)&ipl,  g_ipl);
    cudaGetSymbolAddress((void**)&l1h,   g_l1h);  cudaGetSymbolAddress((void**)&l1l,  g_l1l);
    cudaGetSymbolAddress((void**)&l2h,   g_l2h);  cudaGetSymbolAddress((void**)&l2l,  g_l2l);

    cudaFuncSetAttribute(gemm_mma<false,true,0,false>,  cudaFuncAttributeMaxDynamicSharedMemorySize, GEMM_SMEM);
    cudaFuncSetAttribute(gemm_mma<false,true,1,false>,  cudaFuncAttributeMaxDynamicSharedMemorySize, GEMM_SMEM);
    cudaFuncSetAttribute(gemm_mma<false,true,2,true>,   cudaFuncAttributeMaxDynamicSharedMemorySize, GEMM_SMEM);
    cudaFuncSetAttribute(gemm_mma<true,false,0,false>,  cudaFuncAttributeMaxDynamicSharedMemorySize, GEMM_SMEM);
    cudaFuncSetAttribute(gemm_mma<false,false,0,false>, cudaFuncAttributeMaxDynamicSharedMemorySize, GEMM_SMEM);

    dim3 blk(256);
    const long long SE  = (long long)SS * EE;
    const long long SQ  = (long long)SS * 1024;
    const long long SS2 = (long long)SS * SS;

    // 0) one-time splits (inputs + weights)
    split_k<<<(ROWS*IN_F+255)/256, 256>>>(src, srch, srcl, ROWS*IN_F);
    split_k<<<(EE*IN_F+255)/256, 256>>>(proj_w, pwh, pwl, EE*IN_F);
    split_k<<<(1024*EE+255)/256, 256>>>(in_proj_w, iph, ipl, 1024*EE);  // q,k rows only
    split_k<<<(FF_DIM*EE+255)/256, 256>>>(lin1_w, l1h, l1l, FF_DIM*EE);
    split_k<<<(EE*FF_DIM+255)/256, 256>>>(lin2_w, l2h, l2l, EE*FF_DIM);

    // 1) input projection -> g_x (fp32)
    gemm_mma<false,true,0,false><<<dim3(EE/128, ROWS/128, 1), blk, GEMM_SMEM>>>(
        srch, srcl, pwh, pwl, proj_b, x, nullptr, nullptr,
        IN_F, IN_F, IN_F, EE, 1, 0, 0, 0, 0, 0, 1.f);

    // 2) BatchNorm (batch stats) + PE (+split)
    bn_part_k<<<64, 512>>>(x, part);
    bn_final_k<<<2, 256>>>(part, stats);
    bn_apply_pe_k<<<(ROWS*EE)/256, 256>>>(x, stats, bn_g, bn_b, xh, xl);

    // 3) distance bias (shared across layers)
    dist_bias_k<<<BB*SS, 256>>>(distances, dist_scale, dbias);

    // 4) layers (shared parameters)
    for (int l = 0; l < NL; l++) {
        // qk = x @ in_proj_w[0:1024]^T + b -> split pair (feeds softmax; keep precise)
        gemm_mma<false,true,1,false><<<dim3(1024/128, ROWS/128, 1), blk, GEMM_SMEM>>>(
            xh, xl, iph, ipl, in_proj_b, nullptr, qkh, qkl,
            EE, EE, EE, 1024, 1, 0, 0, 0, 0, 0, 1.f);

        // scores[b,h] = (Q_bh @ K_bh^T) * 1/sqrt(HD)  (full 3-pass precision)
        gemm_mma<false,true,0,false><<<dim3(SS/128, SS/128, BB*HH), blk, GEMM_SMEM>>>(
            qkh, qkl, qkh + EE, qkl + EE, nullptr, sc, nullptr, nullptr,
            HD, 1024, 1024, SS, HH, SQ, HD, SQ, HD, SS2, 0.125f);

        // softmax/head-avg/dist-bias/renorm -> single fp16 w
        attn_w_k<<<BB*SS, 256>>>(sc, dbias, wh);

        // attn_out = w @ x  (w single fp16, x split: 2 MMA passes)
        gemm_mma<true,false,0,false><<<dim3(EE/128, SS/128, BB), blk, GEMM_SMEM>>>(
            wh, nullptr, xh, xl, nullptr, attn, nullptr, nullptr,
            SS, SS, EE, EE, 1, SS2, 0, SE, 0, SE, 1.f);

        // x = LN(x + attn_out) (+split)
        add_ln_k<true><<<ROWS, 256>>>(x, attn, n1_g, n1_b, x, xh, xl);

        // FFN: ff1 relu -> single fp16; ff2 (ff single, weight split: 2 passes)
        gemm_mma<false,true,2,true><<<dim3(FF_DIM/128, ROWS/128, 1), blk, GEMM_SMEM>>>(
            xh, xl, l1h, l1l, lin1_b, nullptr, ffh, nullptr,
            EE, EE, EE, FF_DIM, 1, 0, 0, 0, 0, 0, 1.f);
        gemm_mma<false,false,0,false><<<dim3(EE/128, ROWS/128, 1), blk, GEMM_SMEM>>>(
            ffh, nullptr, l2h, l2l, lin2_b, attn, nullptr, nullptr,
            FF_DIM, FF_DIM, FF_DIM, EE, 1, 0, 0, 0, 0, 0, 1.f);

        // x = LN(x + ff); last layer -> d_out
        if (l == NL - 1)
            add_ln_k<false><<<ROWS, 256>>>(x, attn, n2_g, n2_b, out, nullptr, nullptr);
        else
            add_ln_k<true><<<ROWS, 256>>>(x, attn, n2_g, n2_b, x, xh, xl);
    }
}

// round 7
// speedup vs baseline: 4.1365x; 1.1629x over previous
#include <cuda_runtime.h>
#include <cuda_fp16.h>
#include <cstdint>

// Problem constants
#define BB 8
#define SS 1024
#define IN_F 128
#define EE 512
#define HH 8
#define HD 64
#define FF_DIM 2048
#define NL 4
#define ROWS (BB*SS)          // 8192
#define EPS 1e-5f

// ---------------- scratch (device globals; no allocations allowed) ----------
__device__ __align__(16) float g_x[ROWS*EE];                   // fp32 residual stream
__device__ __align__(16) __half g_scores[(size_t)BB*HH*SS*SS]; // 128 MB fp16 scores
__device__ __align__(16) float g_dbias[(size_t)BB*SS*SS];      // 32 MB
__device__ __align__(16) float g_attn[ROWS*EE];                // 16 MB
__device__ __align__(16) float g_part[2*64*EE];
__device__ __align__(16) float g_stats[2*EE];
// split (hi/lo fp16) operand buffers
__device__ __align__(16) __half g_srch[ROWS*IN_F],  g_srcl[ROWS*IN_F];
__device__ __align__(16) __half g_xh[ROWS*EE],      g_xl[ROWS*EE];
__device__ __align__(16) __half g_qkh[ROWS*1024],   g_qkl[ROWS*1024];
__device__ __align__(16) __half g_wh[(size_t)BB*SS*SS];        // single fp16 attn weights
__device__ __align__(16) __half g_ffh[ROWS*FF_DIM];            // single fp16 relu acts
__device__ __align__(16) __half g_pwh[EE*IN_F],     g_pwl[EE*IN_F];
__device__ __align__(16) __half g_iph[1024*EE],     g_ipl[1024*EE];
__device__ __align__(16) __half g_l1h[FF_DIM*EE],   g_l1l[FF_DIM*EE];
__device__ __align__(16) __half g_l2h[EE*FF_DIM],   g_l2l[EE*FF_DIM];

// ====================== helpers =============================================
__device__ __forceinline__ uint32_t smem_u32(const void* p){
    uint32_t a;
    asm("{ .reg .u64 t; cvta.to.shared.u64 t, %1; cvt.u32.u64 %0, t; }"
        : "=r"(a) : "l"(p));
    return a;
}
__device__ __forceinline__ void ldsm4(uint32_t& r0, uint32_t& r1, uint32_t& r2, uint32_t& r3,
                                      uint32_t addr){
    asm volatile("ldmatrix.sync.aligned.m8n8.x4.shared.b16 {%0,%1,%2,%3}, [%4];"
                 : "=r"(r0), "=r"(r1), "=r"(r2), "=r"(r3) : "r"(addr));
}
__device__ __forceinline__ void ldsm4t(uint32_t& r0, uint32_t& r1, uint32_t& r2, uint32_t& r3,
                                       uint32_t addr){
    asm volatile("ldmatrix.sync.aligned.m8n8.x4.trans.shared.b16 {%0,%1,%2,%3}, [%4];"
                 : "=r"(r0), "=r"(r1), "=r"(r2), "=r"(r3) : "r"(addr));
}
__device__ __forceinline__ void mma16816(float* c, const uint32_t* a, const uint32_t* b){
    asm volatile("mma.sync.aligned.m16n8k16.row.col.f32.f16.f16.f32 "
                 "{%0,%1,%2,%3}, {%4,%5,%6,%7}, {%8,%9}, {%0,%1,%2,%3};"
                 : "+f"(c[0]), "+f"(c[1]), "+f"(c[2]), "+f"(c[3])
                 : "r"(a[0]), "r"(a[1]), "r"(a[2]), "r"(a[3]), "r"(b[0]), "r"(b[1]));
}
#define CP16(d,s)   asm volatile("cp.async.cg.shared.global [%0], [%1], 16;" :: "r"(d), "l"(s) : "memory")
#define CPCOMMIT()  asm volatile("cp.async.commit_group;" ::: "memory")
#define CPWAIT1()   asm volatile("cp.async.wait_group 1;" ::: "memory")

// block reductions (256 threads)
__device__ __forceinline__ float brsum(float v, float* red, int tid){
    #pragma unroll
    for (int o = 16; o; o >>= 1) v += __shfl_xor_sync(0xffffffffu, v, o);
    if ((tid & 31) == 0) red[tid >> 5] = v;
    __syncthreads();
    if (tid < 32) {
        float x = (tid < 8) ? red[tid] : 0.f;
        #pragma unroll
        for (int o = 4; o; o >>= 1) x += __shfl_xor_sync(0xffffffffu, x, o);
        if (tid == 0) red[0] = x;
    }
    __syncthreads();
    v = red[0];
    __syncthreads();
    return v;
}
__device__ __forceinline__ float brmax(float v, float* red, int tid){
    #pragma unroll
    for (int o = 16; o; o >>= 1) v = fmaxf(v, __shfl_xor_sync(0xffffffffu, v, o));
    if ((tid & 31) == 0) red[tid >> 5] = v;
    __syncthreads();
    if (tid < 32) {
        float x = (tid < 8) ? red[tid] : -1e30f;
        #pragma unroll
        for (int o = 4; o; o >>= 1) x = fmaxf(x, __shfl_xor_sync(0xffffffffu, x, o));
        if (tid == 0) red[0] = x;
    }
    __syncthreads();
    v = red[0];
    __syncthreads();
    return v;
}

// ====================== fp16 multi-pass mma.sync GEMM =======================
// C = alpha * A*B (+bias) (+relu).
// ASPLIT=true : A hi+lo -> 3 passes (AhBh + AhBl + AlBh). false: 2 passes.
// BTRANS=false: B [N,K] row-major split (NT). BTRANS=true: B [K,N] (NN, trans).
// OUT: 0 fp32, 1 split pair, 2 single fp16.
#define GEMM_SMEM (3*32768)

template<bool BTRANS, bool ASPLIT, int OUT, bool RELU>
__global__ __launch_bounds__(256,2) void gemm_mma(
    const __half* __restrict__ Ah_, const __half* __restrict__ Al_,
    const __half* __restrict__ Bh_, const __half* __restrict__ Bl_,
    const float* __restrict__ bias,
    float* __restrict__ Cf, __half* __restrict__ Ch, __half* __restrict__ Cl,
    int K, int lda, int ldb, int ldc,
    int hdiv, long long sA0, long long sA1, long long sB0, long long sB1,
    long long sC, float alpha)
{
    extern __shared__ char sm[];
    int tid = threadIdx.x, lane = tid & 31, wid = tid >> 5;
    int z = blockIdx.z;
    long long aoff = (long long)(z / hdiv) * sA0 + (long long)(z % hdiv) * sA1;
    long long boff = (long long)(z / hdiv) * sB0 + (long long)(z % hdiv) * sB1;
    const __half* Ah = Ah_ + aoff;
    const __half* Al = ASPLIT ? (Al_ + aoff) : nullptr;
    const __half* Bh = Bh_ + boff;
    const __half* Bl = Bl_ + boff;
    int m0 = blockIdx.y * 128, n0 = blockIdx.x * 128;
    int wm0 = (wid >> 2) * 64, wn0 = (wid & 3) * 32;

    float acc[4][4][4];
    #pragma unroll
    for (int i = 0; i < 4; i++)
        #pragma unroll
        for (int j = 0; j < 4; j++)
            #pragma unroll
            for (int e = 0; e < 4; e++) acc[i][j][e] = 0.f;

    uint32_t smBase = smem_u32(sm);
    int nch = K >> 5;

    auto stage = [&](int c, int s){
        uint32_t bs = smBase + s * 32768;
        int k0 = c * 32;
        #pragma unroll
        for (int j = 0; j < 2; j++) {
            int id = tid + j * 256;
            int r = id >> 2, cc = id & 3;
            uint32_t d = bs + (uint32_t)(r * 64 + ((cc ^ ((r >> 1) & 3)) << 4));
            CP16(d, Ah + (long long)(m0 + r) * lda + k0 + cc * 8);
            if (ASPLIT) CP16(d + 8192, Al + (long long)(m0 + r) * lda + k0 + cc * 8);
        }
        if (!BTRANS) {
            #pragma unroll
            for (int j = 0; j < 2; j++) {
                int id = tid + j * 256;
                int r = id >> 2, cc = id & 3;
                uint32_t d = bs + 16384 + (uint32_t)(r * 64 + ((cc ^ ((r >> 1) & 3)) << 4));
                CP16(d, Bh + (long long)(n0 + r) * ldb + k0 + cc * 8);
                CP16(d + 8192, Bl + (long long)(n0 + r) * ldb + k0 + cc * 8);
            }
        } else {
            #pragma unroll
            for (int j = 0; j < 2; j++) {
                int id = tid + j * 256;
                int k = id >> 4, cc = id & 15;
                uint32_t d = bs + 16384 + (uint32_t)(k * 256 + ((cc ^ (k & 7)) << 4));
                CP16(d, Bh + (long long)(k0 + k) * ldb + n0 + cc * 8);
                CP16(d + 8192, Bl + (long long)(k0 + k) * ldb + n0 + cc * 8);
            }
        }
        CPCOMMIT();
    };

    stage(0, 0);
    if (nch > 1) stage(1, 1); else CPCOMMIT();

    uint32_t aRowB = (uint32_t)(wm0 + (lane & 15)) * 64;
    uint32_t aXor  = ((uint32_t)(lane & 15) >> 1) & 3;
    uint32_t aG    = (uint32_t)(lane >> 4);
    uint32_t bRowB = (uint32_t)(wn0 + ((lane >> 4) << 3) + (lane & 7)) * 64;
    uint32_t bXor  = (((uint32_t)lane & 7) >> 1) & 3;
    uint32_t bG    = (uint32_t)((lane >> 3) & 1);
    uint32_t btRow = ((((uint32_t)lane >> 3) & 1) * 8 + ((uint32_t)lane & 7)) * 256;
    uint32_t btNc  = ((uint32_t)wn0 >> 3) + ((uint32_t)lane >> 4);
    uint32_t btXk  = (uint32_t)lane & 7;

    for (int c = 0; c < nch; c++) {
        CPWAIT1();
        __syncthreads();
        uint32_t base = smBase + (uint32_t)((c % 3) * 32768);
        #pragma unroll
        for (int ks = 0; ks < 2; ks++) {
            uint32_t bh[8], bl[8];
            if (!BTRANS) {
                #pragma unroll
                for (int ntp = 0; ntp < 2; ntp++) {
                    uint32_t ga = (uint32_t)(ks * 2) + bG;
                    uint32_t off = bRowB + (uint32_t)(ntp * 1024) + ((ga ^ bXor) << 4);
                    ldsm4(bh[ntp*4+0], bh[ntp*4+1], bh[ntp*4+2], bh[ntp*4+3], base + 16384 + off);
                    ldsm4(bl[ntp*4+0], bl[ntp*4+1], bl[ntp*4+2], bl[ntp*4+3], base + 24576 + off);
                }
            } else {
                #pragma unroll
                for (int ntp = 0; ntp < 2; ntp++) {
                    uint32_t off = btRow + (uint32_t)(ks * 4096)
                                 + (((btNc + (uint32_t)(ntp * 2)) ^ btXk) << 4);
                    ldsm4t(bh[ntp*4+0], bh[ntp*4+1], bh[ntp*4+2], bh[ntp*4+3], base + 16384 + off);
                    ldsm4t(bl[ntp*4+0], bl[ntp*4+1], bl[ntp*4+2], bl[ntp*4+3], base + 24576 + off);
                }
            }
            #pragma unroll
            for (int mt = 0; mt < 4; mt++) {
                uint32_t ga = (uint32_t)(ks * 2) + aG;
                uint32_t off = aRowB + (uint32_t)(mt * 1024) + ((ga ^ aXor) << 4);
                uint32_t ah[4], al[4];
                ldsm4(ah[0], ah[1], ah[2], ah[3], base + off);
                if (ASPLIT) ldsm4(al[0], al[1], al[2], al[3], base + 8192 + off);
                #pragma unroll
                for (int nt = 0; nt < 4; nt++) {
                    const uint32_t* ph = &bh[(nt >> 1) * 4 + (nt & 1) * 2];
                    const uint32_t* pl = &bl[(nt >> 1) * 4 + (nt & 1) * 2];
                    mma16816(acc[mt][nt], ah, ph);
                    mma16816(acc[mt][nt], ah, pl);
                    if (ASPLIT) mma16816(acc[mt][nt], al, ph);
                }
            }
        }
        if (c + 2 < nch) stage(c + 2, (c + 2) % 3); else CPCOMMIT();
    }

    // ---- epilogue ----
    #pragma unroll
    for (int nt = 0; nt < 4; nt++) {
        int cc = n0 + wn0 + nt * 8 + (lane & 3) * 2;
        float b0 = 0.f, b1 = 0.f;
        if (bias) { b0 = bias[cc]; b1 = bias[cc + 1]; }
        #pragma unroll
        for (int mt = 0; mt < 4; mt++) {
            int r = m0 + wm0 + mt * 16 + (lane >> 2);
            float v0 = acc[mt][nt][0] * alpha + b0;
            float v1 = acc[mt][nt][1] * alpha + b1;
            float v2 = acc[mt][nt][2] * alpha + b0;
            float v3 = acc[mt][nt][3] * alpha + b1;
            if (RELU) { v0 = fmaxf(v0,0.f); v1 = fmaxf(v1,0.f); v2 = fmaxf(v2,0.f); v3 = fmaxf(v3,0.f); }
            if (OUT == 0) {
                float* p = Cf + (long long)z * sC;
                *(float2*)(p + (long long)r * ldc + cc)       = make_float2(v0, v1);
                *(float2*)(p + (long long)(r + 8) * ldc + cc) = make_float2(v2, v3);
            } else if (OUT == 1) {
                __half h0 = __float2half_rn(v0), h1 = __float2half_rn(v1);
                __half h2 = __float2half_rn(v2), h3 = __float2half_rn(v3);
                __half* ph = Ch + (long long)z * sC;
                __half* pl = Cl + (long long)z * sC;
                *(__half2*)(ph + (long long)r * ldc + cc)       = __halves2half2(h0, h1);
                *(__half2*)(ph + (long long)(r + 8) * ldc + cc) = __halves2half2(h2, h3);
                *(__half2*)(pl + (long long)r * ldc + cc) =
                    __halves2half2(__float2half_rn(v0 - __half2float(h0)),
                                   __float2half_rn(v1 - __half2float(h1)));
                *(__half2*)(pl + (long long)(r + 8) * ldc + cc) =
                    __halves2half2(__float2half_rn(v2 - __half2float(h2)),
                                   __float2half_rn(v3 - __half2float(h3)));
            } else {
                __half* ph = Ch + (long long)z * sC;
                *(__half2*)(ph + (long long)r * ldc + cc) =
                    __halves2half2(__float2half_rn(v0), __float2half_rn(v1));
                *(__half2*)(ph + (long long)(r + 8) * ldc + cc) =
                    __halves2half2(__float2half_rn(v2), __float2half_rn(v3));
            }
        }
    }
}

// ---------------- fp32 -> fp16 hi/lo splitter --------------------------------
__global__ void split_k(const float* __restrict__ in, __half* __restrict__ h,
                        __half* __restrict__ l, int n) {
    int i = blockIdx.x * 256 + threadIdx.x;
    if (i < n) {
        float v = in[i];
        __half hv = __float2half_rn(v);
        h[i] = hv;
        l[i] = __float2half_rn(v - __half2float(hv));
    }
}

// ---------------- BatchNorm (training-mode batch stats), deterministic -----
__global__ void bn_part_k(const float* __restrict__ x, float* __restrict__ part) {
    int e = threadIdx.x;
    int blk = blockIdx.x;
    float s = 0.f, sq = 0.f;
    int r0 = blk * 128;
    for (int r = r0; r < r0 + 128; r++) {
        float v = x[(long long)r * EE + e];
        s += v; sq += v * v;
    }
    part[blk * EE + e] = s;
    part[(64 + blk) * EE + e] = sq;
}

__global__ void bn_final_k(const float* __restrict__ part, float* __restrict__ stats) {
    int e = blockIdx.x * blockDim.x + threadIdx.x;
    float s = 0.f, sq = 0.f;
    for (int i = 0; i < 64; i++) {
        s  += part[i * EE + e];
        sq += part[(64 + i) * EE + e];
    }
    float mu = s / (float)ROWS;
    stats[e] = mu;
    stats[EE + e] = sq / (float)ROWS - mu * mu;
}

__global__ void bn_apply_pe_k(float* __restrict__ x, const float* __restrict__ stats,
                              const float* __restrict__ g, const float* __restrict__ b,
                              __half* __restrict__ xh, __half* __restrict__ xl) {
    long long idx = (long long)blockIdx.x * blockDim.x + threadIdx.x;
    int e = (int)(idx & (EE - 1));
    long long r = idx >> 9;
    int s = (int)(r & (SS - 1));
    float mu = stats[e], var = stats[EE + e];
    int j = e >> 1;
    float dt = expf((float)(2 * j) * (-9.210340371976184f / (float)EE));
    float ang = (float)s * dt;
    float pe = (e & 1) ? cosf(ang) : sinf(ang);
    float v = (x[idx] - mu) * rsqrtf(var + EPS) * g[e] + b[e] + pe;
    x[idx] = v;
    __half hv = __float2half_rn(v);
    xh[idx] = hv;
    xl[idx] = __float2half_rn(v - __half2float(hv));
}

// ---------------- distance bias ---------------------------------------------
__global__ void dist_bias_k(const float* __restrict__ d, const float* __restrict__ scale_p,
                            float* __restrict__ bias) {
    int bq = blockIdx.x;
    int tid = threadIdx.x;
    __shared__ float red[8];
    float4 v = *(const float4*)(d + (long long)bq * SS + tid * 4);
    float mx = brmax(fmaxf(fmaxf(v.x, v.y), fmaxf(v.z, v.w)), red, tid);
    float inv_dmax = 1.f / mx;
    float sc = scale_p[0];
    float4 o;
    o.x = expf(sc * (1.f - v.x * inv_dmax));
    o.y = expf(sc * (1.f - v.y * inv_dmax));
    o.z = expf(sc * (1.f - v.z * inv_dmax));
    o.w = expf(sc * (1.f - v.w * inv_dmax));
    *(float4*)(bias + (long long)bq * SS + tid * 4) = o;
}

// ---------------- softmax per head (fp16 scores), head-avg, renorm ----------
__global__ void attn_w_k(const __half* __restrict__ scores, const float* __restrict__ dbias,
                         __half* __restrict__ wh) {
    int bq = blockIdx.x;
    int b = bq >> 10, q = bq & (SS - 1);
    int tid = threadIdx.x;
    __shared__ float red[8];
    float w0 = 0.f, w1 = 0.f, w2 = 0.f, w3 = 0.f;
    const __half* sp = scores + ((long long)b * HH * SS + q) * SS + tid * 4;
    #pragma unroll 1
    for (int h = 0; h < HH; h++) {
        uint2 raw = *(const uint2*)(sp + (long long)h * SS * SS);
        float2 f0 = __half22float2(*reinterpret_cast<__half2*>(&raw.x));
        float2 f1 = __half22float2(*reinterpret_cast<__half2*>(&raw.y));
        float mx = brmax(fmaxf(fmaxf(f0.x, f0.y), fmaxf(f1.x, f1.y)), red, tid);
        float e0 = __expf(f0.x - mx), e1 = __expf(f0.y - mx);
        float e2 = __expf(f1.x - mx), e3 = __expf(f1.y - mx);
        float s = brsum(e0 + e1 + e2 + e3, red, tid);
        float inv = 1.f / s;
        w0 += e0 * inv; w1 += e1 * inv; w2 += e2 * inv; w3 += e3 * inv;
    }
    float4 db = *(const float4*)(dbias + (long long)bq * SS + tid * 4);
    w0 *= db.x; w1 *= db.y; w2 *= db.z; w3 *= db.w;
    float s = brsum(w0 + w1 + w2 + w3, red, tid);
    float inv = 1.f / s;
    long long o = (long long)bq * SS + tid * 4;
    *(__half2*)(wh + o)     = __halves2half2(__float2half_rn(w0 * inv), __float2half_rn(w1 * inv));
    *(__half2*)(wh + o + 2) = __halves2half2(__float2half_rn(w2 * inv), __float2half_rn(w3 * inv));
}

// ---------------- fused residual + LayerNorm (+optional split) --------------
template<bool SPLIT>
__global__ void add_ln_k(const float* __restrict__ x, const float* __restrict__ r,
                         const float* __restrict__ g, const float* __restrict__ b,
                         float* __restrict__ out, __half* __restrict__ oh,
                         __half* __restrict__ ol) {
    int row = blockIdx.x;
    int tid = threadIdx.x;
    __shared__ float red[8];
    long long base = (long long)row * EE;
    float2 v = *(const float2*)(x + base + tid * 2);
    float2 rr = *(const float2*)(r + base + tid * 2);
    v.x += rr.x; v.y += rr.y;
    float mean = brsum(v.x + v.y, red, tid) * (1.f / (float)EE);
    float var = brsum(v.x * v.x + v.y * v.y, red, tid) * (1.f / (float)EE) - mean * mean;
    float inv = rsqrtf(var + EPS);
    float2 gg = *(const float2*)(g + tid * 2);
    float2 bb = *(const float2*)(b + tid * 2);
    float o0 = (v.x - mean) * inv * gg.x + bb.x;
    float o1 = (v.y - mean) * inv * gg.y + bb.y;
    *(float2*)(out + base + tid * 2) = make_float2(o0, o1);
    if (SPLIT) {
        __half h0 = __float2half_rn(o0), h1 = __float2half_rn(o1);
        *(__half2*)(oh + base + tid * 2) = __halves2half2(h0, h1);
        *(__half2*)(ol + base + tid * 2) =
            __halves2half2(__float2half_rn(o0 - __half2float(h0)),
                           __float2half_rn(o1 - __half2float(h1)));
    }
}

// ---------------- launch -----------------------------------------------------
extern "C" void kernel_launch(void* const* d_in, const int* in_sizes, int n_in,
                              void* d_out, int out_size) {
    (void)in_sizes; (void)n_in; (void)out_size;
    const float* src        = (const float*)d_in[0];
    const float* distances  = (const float*)d_in[1];
    const float* proj_w     = (const float*)d_in[2];
    const float* proj_b     = (const float*)d_in[3];
    const float* bn_g       = (const float*)d_in[4];
    const float* bn_b       = (const float*)d_in[5];
    const float* in_proj_w  = (const float*)d_in[6];
    const float* in_proj_b  = (const float*)d_in[7];
    const float* dist_scale = (const float*)d_in[8];
    const float* lin1_w     = (const float*)d_in[9];
    const float* lin1_b     = (const float*)d_in[10];
    const float* lin2_w     = (const float*)d_in[11];
    const float* lin2_b     = (const float*)d_in[12];
    const float* n1_g       = (const float*)d_in[13];
    const float* n1_b       = (const float*)d_in[14];
    const float* n2_g       = (const float*)d_in[15];
    const float* n2_b       = (const float*)d_in[16];
    float* out = (float*)d_out;

    float *x, *dbias, *attn, *part, *stats;
    __half *sc, *srch,*srcl,*xh,*xl,*qkh,*qkl,*wh,*ffh;
    __half *pwh,*pwl,*iph,*ipl,*l1h,*l1l,*l2h,*l2l;
    cudaGetSymbolAddress((void**)&x,     g_x);
    cudaGetSymbolAddress((void**)&sc,    g_scores);
    cudaGetSymbolAddress((void**)&dbias, g_dbias);
    cudaGetSymbolAddress((void**)&attn,  g_attn);
    cudaGetSymbolAddress((void**)&part,  g_part);
    cudaGetSymbolAddress((void**)&stats, g_stats);
    cudaGetSymbolAddress((void**)&srch,  g_srch); cudaGetSymbolAddress((void**)&srcl, g_srcl);
    cudaGetSymbolAddress((void**)&xh,    g_xh);   cudaGetSymbolAddress((void**)&xl,   g_xl);
    cudaGetSymbolAddress((void**)&qkh,   g_qkh);  cudaGetSymbolAddress((void**)&qkl,  g_qkl);
    cudaGetSymbolAddress((void**)&wh,    g_wh);
    cudaGetSymbolAddress((void**)&ffh,   g_ffh);
    cudaGetSymbolAddress((void**)&pwh,   g_pwh);  cudaGetSymbolAddress((void**)&pwl,  g_pwl);
    cudaGetSymbolAddress((void**)&iph,   g_iph);  cudaGetSymbolAddress((void**)&ipl,  g_ipl);
    cudaGetSymbolAddress((void**)&l1h,   g_l1h);  cudaGetSymbolAddress((void**)&l1l,  g_l1l);
    cudaGetSymbolAddress((void**)&l2h,   g_l2h);  cudaGetSymbolAddress((void**)&l2l,  g_l2l);

    cudaFuncSetAttribute(gemm_mma<false,true,0,false>,  cudaFuncAttributeMaxDynamicSharedMemorySize, GEMM_SMEM);
    cudaFuncSetAttribute(gemm_mma<false,false,1,false>, cudaFuncAttributeMaxDynamicSharedMemorySize, GEMM_SMEM);
    cudaFuncSetAttribute(gemm_mma<false,false,2,false>, cudaFuncAttributeMaxDynamicSharedMemorySize, GEMM_SMEM);
    cudaFuncSetAttribute(gemm_mma<false,false,2,true>,  cudaFuncAttributeMaxDynamicSharedMemorySize, GEMM_SMEM);
    cudaFuncSetAttribute(gemm_mma<true,false,0,false>,  cudaFuncAttributeMaxDynamicSharedMemorySize, GEMM_SMEM);
    cudaFuncSetAttribute(gemm_mma<false,false,0,false>, cudaFuncAttributeMaxDynamicSharedMemorySize, GEMM_SMEM);

    dim3 blk(256);
    const long long SE  = (long long)SS * EE;
    const long long SQ  = (long long)SS * 1024;
    const long long SS2 = (long long)SS * SS;

    // 0) one-time splits (inputs + weights)
    split_k<<<(ROWS*IN_F+255)/256, 256>>>(src, srch, srcl, ROWS*IN_F);
    split_k<<<(EE*IN_F+255)/256, 256>>>(proj_w, pwh, pwl, EE*IN_F);
    split_k<<<(1024*EE+255)/256, 256>>>(in_proj_w, iph, ipl, 1024*EE);  // q,k rows only
    split_k<<<(FF_DIM*EE+255)/256, 256>>>(lin1_w, l1h, l1l, FF_DIM*EE);
    split_k<<<(EE*FF_DIM+255)/256, 256>>>(lin2_w, l2h, l2l, EE*FF_DIM);

    // 1) input projection -> g_x (fp32), keep full 3-pass (cheap)
    gemm_mma<false,true,0,false><<<dim3(EE/128, ROWS/128, 1), blk, GEMM_SMEM>>>(
        srch, srcl, pwh, pwl, proj_b, x, nullptr, nullptr,
        IN_F, IN_F, IN_F, EE, 1, 0, 0, 0, 0, 0, 1.f);

    // 2) BatchNorm (batch stats) + PE (+split)
    bn_part_k<<<64, 512>>>(x, part);
    bn_final_k<<<2, 256>>>(part, stats);
    bn_apply_pe_k<<<(ROWS*EE)/256, 256>>>(x, stats, bn_g, bn_b, xh, xl);

    // 3) distance bias (shared across layers)
    dist_bias_k<<<BB*SS, 256>>>(distances, dist_scale, dbias);

    // 4) layers (shared parameters)
    for (int l = 0; l < NL; l++) {
        // qk = x @ in_proj_w[0:1024]^T + b -> split pair (2-pass: xh only)
        gemm_mma<false,false,1,false><<<dim3(1024/128, ROWS/128, 1), blk, GEMM_SMEM>>>(
            xh, nullptr, iph, ipl, in_proj_b, nullptr, qkh, qkl,
            EE, EE, EE, 1024, 1, 0, 0, 0, 0, 0, 1.f);

        // scores[b,h] = (Q_bh @ K_bh^T) * 1/sqrt(HD) -> fp16 (2-pass: qh x (kh,kl))
        gemm_mma<false,false,2,false><<<dim3(SS/128, SS/128, BB*HH), blk, GEMM_SMEM>>>(
            qkh, nullptr, qkh + EE, qkl + EE, nullptr, nullptr, sc, nullptr,
            HD, 1024, 1024, SS, HH, SQ, HD, SQ, HD, SS2, 0.125f);

        // softmax/head-avg/dist-bias/renorm -> single fp16 w
        attn_w_k<<<BB*SS, 256>>>(sc, dbias, wh);

        // attn_out = w @ x  (w single fp16, x split: 2 passes)
        gemm_mma<true,false,0,false><<<dim3(EE/128, SS/128, BB), blk, GEMM_SMEM>>>(
            wh, nullptr, xh, xl, nullptr, attn, nullptr, nullptr,
            SS, SS, EE, EE, 1, SS2, 0, SE, 0, SE, 1.f);

        // x = LN(x + attn_out) (+split)
        add_ln_k<true><<<ROWS, 256>>>(x, attn, n1_g, n1_b, x, xh, xl);

        // FFN: ff1 relu -> single fp16 (2-pass); ff2 (2-pass) -> fp32
        gemm_mma<false,false,2,true><<<dim3(FF_DIM/128, ROWS/128, 1), blk, GEMM_SMEM>>>(
            xh, nullptr, l1h, l1l, lin1_b, nullptr, ffh, nullptr,
            EE, EE, EE, FF_DIM, 1, 0, 0, 0, 0, 0, 1.f);
        gemm_mma<false,false,0,false><<<dim3(EE/128, ROWS/128, 1), blk, GEMM_SMEM>>>(
            ffh, nullptr, l2h, l2l, lin2_b, attn, nullptr, nullptr,
            FF_DIM, FF_DIM, FF_DIM, EE, 1, 0, 0, 0, 0, 0, 1.f);

        // x = LN(x + ff); last layer -> d_out
        if (l == NL - 1)
            add_ln_k<false><<<ROWS, 256>>>(x, attn, n2_g, n2_b, out, nullptr, nullptr);
        else
            add_ln_k<true><<<ROWS, 256>>>(x, attn, n2_g, n2_b, x, xh, xl);
    }
}

// round 8
// speedup vs baseline: 6.3138x; 1.5263x over previous
#include <cuda_runtime.h>
#include <cuda_fp16.h>
#include <cstdint>

// Problem constants
#define BB 8
#define SS 1024
#define IN_F 128
#define EE 512
#define HH 8
#define HD 64
#define FF_DIM 2048
#define NL 4
#define ROWS (BB*SS)          // 8192
#define EPS 1e-5f

// ---------------- scratch (device globals; no allocations allowed) ----------
__device__ __align__(16) float g_x[ROWS*EE];                   // fp32 residual stream
__device__ __align__(16) __half g_scores[(size_t)BB*HH*SS*SS]; // 128 MB fp16 scores
__device__ __align__(16) __half g_dbias[(size_t)BB*SS*SS];     // 16 MB fp16 dist bias
__device__ __align__(16) float g_attn[ROWS*EE];                // 16 MB
__device__ __align__(16) float g_part[2*64*EE];
__device__ __align__(16) float g_stats[2*EE];
// fp16 operand buffers
__device__ __align__(16) __half g_srch[ROWS*IN_F],  g_srcl[ROWS*IN_F];  // split (proj 3-pass)
__device__ __align__(16) __half g_xh[ROWS*EE];
__device__ __align__(16) __half g_qkh[ROWS*1024];
__device__ __align__(16) __half g_wh[(size_t)BB*SS*SS];
__device__ __align__(16) __half g_ffh[ROWS*FF_DIM];
__device__ __align__(16) __half g_pwh[EE*IN_F],     g_pwl[EE*IN_F];     // split (proj 3-pass)
__device__ __align__(16) __half g_iph[1024*EE];
__device__ __align__(16) __half g_l1h[FF_DIM*EE];
__device__ __align__(16) __half g_l2h[EE*FF_DIM];

// ====================== helpers =============================================
__device__ __forceinline__ uint32_t smem_u32(const void* p){
    uint32_t a;
    asm("{ .reg .u64 t; cvta.to.shared.u64 t, %1; cvt.u32.u64 %0, t; }"
        : "=r"(a) : "l"(p));
    return a;
}
__device__ __forceinline__ void ldsm4(uint32_t& r0, uint32_t& r1, uint32_t& r2, uint32_t& r3,
                                      uint32_t addr){
    asm volatile("ldmatrix.sync.aligned.m8n8.x4.shared.b16 {%0,%1,%2,%3}, [%4];"
                 : "=r"(r0), "=r"(r1), "=r"(r2), "=r"(r3) : "r"(addr));
}
__device__ __forceinline__ void ldsm4t(uint32_t& r0, uint32_t& r1, uint32_t& r2, uint32_t& r3,
                                       uint32_t addr){
    asm volatile("ldmatrix.sync.aligned.m8n8.x4.trans.shared.b16 {%0,%1,%2,%3}, [%4];"
                 : "=r"(r0), "=r"(r1), "=r"(r2), "=r"(r3) : "r"(addr));
}
__device__ __forceinline__ void mma16816(float* c, const uint32_t* a, const uint32_t* b){
    asm volatile("mma.sync.aligned.m16n8k16.row.col.f32.f16.f16.f32 "
                 "{%0,%1,%2,%3}, {%4,%5,%6,%7}, {%8,%9}, {%0,%1,%2,%3};"
                 : "+f"(c[0]), "+f"(c[1]), "+f"(c[2]), "+f"(c[3])
                 : "r"(a[0]), "r"(a[1]), "r"(a[2]), "r"(a[3]), "r"(b[0]), "r"(b[1]));
}
#define CP16(d,s)   asm volatile("cp.async.cg.shared.global [%0], [%1], 16;" :: "r"(d), "l"(s) : "memory")
#define CPCOMMIT()  asm volatile("cp.async.commit_group;" ::: "memory")
#define CPWAIT1()   asm volatile("cp.async.wait_group 1;" ::: "memory")

__device__ __forceinline__ float wrsum(float v){
    #pragma unroll
    for (int o = 16; o; o >>= 1) v += __shfl_xor_sync(0xffffffffu, v, o);
    return v;
}
__device__ __forceinline__ float wrmax(float v){
    #pragma unroll
    for (int o = 16; o; o >>= 1) v = fmaxf(v, __shfl_xor_sync(0xffffffffu, v, o));
    return v;
}

// ====================== fp16 multi-pass mma.sync GEMM =======================
// C = alpha * A*B (+bias) (+relu).
// ASPLIT: A has lo plane (adds AlBh pass). BSPLIT: B has lo plane (adds AhBl).
// BTRANS=false: B [N,K] row-major (NT). BTRANS=true: B [K,N] (NN, ldmatrix.trans).
// OUT: 0 fp32, 2 single fp16.
#define GEMM_SMEM (3*32768)

template<bool BTRANS, bool ASPLIT, bool BSPLIT, int OUT, bool RELU>
__global__ __launch_bounds__(256,2) void gemm_mma(
    const __half* __restrict__ Ah_, const __half* __restrict__ Al_,
    const __half* __restrict__ Bh_, const __half* __restrict__ Bl_,
    const float* __restrict__ bias,
    float* __restrict__ Cf, __half* __restrict__ Ch,
    int K, int lda, int ldb, int ldc,
    int hdiv, long long sA0, long long sA1, long long sB0, long long sB1,
    long long sC, float alpha)
{
    extern __shared__ char sm[];
    int tid = threadIdx.x, lane = tid & 31, wid = tid >> 5;
    int z = blockIdx.z;
    long long aoff = (long long)(z / hdiv) * sA0 + (long long)(z % hdiv) * sA1;
    long long boff = (long long)(z / hdiv) * sB0 + (long long)(z % hdiv) * sB1;
    const __half* Ah = Ah_ + aoff;
    const __half* Al = ASPLIT ? (Al_ + aoff) : nullptr;
    const __half* Bh = Bh_ + boff;
    const __half* Bl = BSPLIT ? (Bl_ + boff) : nullptr;
    int m0 = blockIdx.y * 128, n0 = blockIdx.x * 128;
    int wm0 = (wid >> 2) * 64, wn0 = (wid & 3) * 32;

    float acc[4][4][4];
    #pragma unroll
    for (int i = 0; i < 4; i++)
        #pragma unroll
        for (int j = 0; j < 4; j++)
            #pragma unroll
            for (int e = 0; e < 4; e++) acc[i][j][e] = 0.f;

    uint32_t smBase = smem_u32(sm);
    int nch = K >> 5;

    auto stage = [&](int c, int s){
        uint32_t bs = smBase + s * 32768;
        int k0 = c * 32;
        #pragma unroll
        for (int j = 0; j < 2; j++) {
            int id = tid + j * 256;
            int r = id >> 2, cc = id & 3;
            uint32_t d = bs + (uint32_t)(r * 64 + ((cc ^ ((r >> 1) & 3)) << 4));
            CP16(d, Ah + (long long)(m0 + r) * lda + k0 + cc * 8);
            if (ASPLIT) CP16(d + 8192, Al + (long long)(m0 + r) * lda + k0 + cc * 8);
        }
        if (!BTRANS) {
            #pragma unroll
            for (int j = 0; j < 2; j++) {
                int id = tid + j * 256;
                int r = id >> 2, cc = id & 3;
                uint32_t d = bs + 16384 + (uint32_t)(r * 64 + ((cc ^ ((r >> 1) & 3)) << 4));
                CP16(d, Bh + (long long)(n0 + r) * ldb + k0 + cc * 8);
                if (BSPLIT) CP16(d + 8192, Bl + (long long)(n0 + r) * ldb + k0 + cc * 8);
            }
        } else {
            #pragma unroll
            for (int j = 0; j < 2; j++) {
                int id = tid + j * 256;
                int k = id >> 4, cc = id & 15;
                uint32_t d = bs + 16384 + (uint32_t)(k * 256 + ((cc ^ (k & 7)) << 4));
                CP16(d, Bh + (long long)(k0 + k) * ldb + n0 + cc * 8);
                if (BSPLIT) CP16(d + 8192, Bl + (long long)(k0 + k) * ldb + n0 + cc * 8);
            }
        }
        CPCOMMIT();
    };

    stage(0, 0);
    if (nch > 1) stage(1, 1); else CPCOMMIT();

    uint32_t aRowB = (uint32_t)(wm0 + (lane & 15)) * 64;
    uint32_t aXor  = ((uint32_t)(lane & 15) >> 1) & 3;
    uint32_t aG    = (uint32_t)(lane >> 4);
    uint32_t bRowB = (uint32_t)(wn0 + ((lane >> 4) << 3) + (lane & 7)) * 64;
    uint32_t bXor  = (((uint32_t)lane & 7) >> 1) & 3;
    uint32_t bG    = (uint32_t)((lane >> 3) & 1);
    uint32_t btRow = ((((uint32_t)lane >> 3) & 1) * 8 + ((uint32_t)lane & 7)) * 256;
    uint32_t btNc  = ((uint32_t)wn0 >> 3) + ((uint32_t)lane >> 4);
    uint32_t btXk  = (uint32_t)lane & 7;

    for (int c = 0; c < nch; c++) {
        CPWAIT1();
        __syncthreads();
        uint32_t base = smBase + (uint32_t)((c % 3) * 32768);
        #pragma unroll
        for (int ks = 0; ks < 2; ks++) {
            uint32_t bh[8], bl[8];
            if (!BTRANS) {
                #pragma unroll
                for (int ntp = 0; ntp < 2; ntp++) {
                    uint32_t ga = (uint32_t)(ks * 2) + bG;
                    uint32_t off = bRowB + (uint32_t)(ntp * 1024) + ((ga ^ bXor) << 4);
                    ldsm4(bh[ntp*4+0], bh[ntp*4+1], bh[ntp*4+2], bh[ntp*4+3], base + 16384 + off);
                    if (BSPLIT)
                        ldsm4(bl[ntp*4+0], bl[ntp*4+1], bl[ntp*4+2], bl[ntp*4+3], base + 24576 + off);
                }
            } else {
                #pragma unroll
                for (int ntp = 0; ntp < 2; ntp++) {
                    uint32_t off = btRow + (uint32_t)(ks * 4096)
                                 + (((btNc + (uint32_t)(ntp * 2)) ^ btXk) << 4);
                    ldsm4t(bh[ntp*4+0], bh[ntp*4+1], bh[ntp*4+2], bh[ntp*4+3], base + 16384 + off);
                    if (BSPLIT)
                        ldsm4t(bl[ntp*4+0], bl[ntp*4+1], bl[ntp*4+2], bl[ntp*4+3], base + 24576 + off);
                }
            }
            #pragma unroll
            for (int mt = 0; mt < 4; mt++) {
                uint32_t ga = (uint32_t)(ks * 2) + aG;
                uint32_t off = aRowB + (uint32_t)(mt * 1024) + ((ga ^ aXor) << 4);
                uint32_t ah[4], al[4];
                ldsm4(ah[0], ah[1], ah[2], ah[3], base + off);
                if (ASPLIT) ldsm4(al[0], al[1], al[2], al[3], base + 8192 + off);
                #pragma unroll
                for (int nt = 0; nt < 4; nt++) {
                    const uint32_t* ph = &bh[(nt >> 1) * 4 + (nt & 1) * 2];
                    const uint32_t* pl = &bl[(nt >> 1) * 4 + (nt & 1) * 2];
                    mma16816(acc[mt][nt], ah, ph);
                    if (BSPLIT) mma16816(acc[mt][nt], ah, pl);
                    if (ASPLIT) mma16816(acc[mt][nt], al, ph);
                }
            }
        }
        if (c + 2 < nch) stage(c + 2, (c + 2) % 3); else CPCOMMIT();
    }

    // ---- epilogue ----
    #pragma unroll
    for (int nt = 0; nt < 4; nt++) {
        int cc = n0 + wn0 + nt * 8 + (lane & 3) * 2;
        float b0 = 0.f, b1 = 0.f;
        if (bias) { b0 = bias[cc]; b1 = bias[cc + 1]; }
        #pragma unroll
        for (int mt = 0; mt < 4; mt++) {
            int r = m0 + wm0 + mt * 16 + (lane >> 2);
            float v0 = acc[mt][nt][0] * alpha + b0;
            float v1 = acc[mt][nt][1] * alpha + b1;
            float v2 = acc[mt][nt][2] * alpha + b0;
            float v3 = acc[mt][nt][3] * alpha + b1;
            if (RELU) { v0 = fmaxf(v0,0.f); v1 = fmaxf(v1,0.f); v2 = fmaxf(v2,0.f); v3 = fmaxf(v3,0.f); }
            if (OUT == 0) {
                float* p = Cf + (long long)z * sC;
                *(float2*)(p + (long long)r * ldc + cc)       = make_float2(v0, v1);
                *(float2*)(p + (long long)(r + 8) * ldc + cc) = make_float2(v2, v3);
            } else {
                __half* ph = Ch + (long long)z * sC;
                *(__half2*)(ph + (long long)r * ldc + cc) =
                    __halves2half2(__float2half_rn(v0), __float2half_rn(v1));
                *(__half2*)(ph + (long long)(r + 8) * ldc + cc) =
                    __halves2half2(__float2half_rn(v2), __float2half_rn(v3));
            }
        }
    }
}

// ---------------- fp32 -> fp16 converters -----------------------------------
__global__ void split_k(const float* __restrict__ in, __half* __restrict__ h,
                        __half* __restrict__ l, int n) {
    int i = blockIdx.x * 256 + threadIdx.x;
    if (i < n) {
        float v = in[i];
        __half hv = __float2half_rn(v);
        h[i] = hv;
        l[i] = __float2half_rn(v - __half2float(hv));
    }
}
__global__ void cvt_k(const float* __restrict__ in, __half* __restrict__ h, int n) {
    int i = blockIdx.x * 256 + threadIdx.x;
    if (i < n) h[i] = __float2half_rn(in[i]);
}

// ---------------- BatchNorm (training-mode batch stats), deterministic -----
__global__ void bn_part_k(const float* __restrict__ x, float* __restrict__ part) {
    int e = threadIdx.x;
    int blk = blockIdx.x;
    float s = 0.f, sq = 0.f;
    int r0 = blk * 128;
    for (int r = r0; r < r0 + 128; r++) {
        float v = x[(long long)r * EE + e];
        s += v; sq += v * v;
    }
    part[blk * EE + e] = s;
    part[(64 + blk) * EE + e] = sq;
}

__global__ void bn_final_k(const float* __restrict__ part, float* __restrict__ stats) {
    int e = blockIdx.x * blockDim.x + threadIdx.x;
    float s = 0.f, sq = 0.f;
    for (int i = 0; i < 64; i++) {
        s  += part[i * EE + e];
        sq += part[(64 + i) * EE + e];
    }
    float mu = s / (float)ROWS;
    stats[e] = mu;
    stats[EE + e] = sq / (float)ROWS - mu * mu;
}

__global__ void bn_apply_pe_k(float* __restrict__ x, const float* __restrict__ stats,
                              const float* __restrict__ g, const float* __restrict__ b,
                              __half* __restrict__ xh) {
    long long idx = (long long)blockIdx.x * blockDim.x + threadIdx.x;
    int e = (int)(idx & (EE - 1));
    long long r = idx >> 9;
    int s = (int)(r & (SS - 1));
    float mu = stats[e], var = stats[EE + e];
    int j = e >> 1;
    float dt = expf((float)(2 * j) * (-9.210340371976184f / (float)EE));
    float ang = (float)s * dt;
    float pe = (e & 1) ? cosf(ang) : sinf(ang);
    float v = (x[idx] - mu) * rsqrtf(var + EPS) * g[e] + b[e] + pe;
    x[idx] = v;
    xh[idx] = __float2half_rn(v);
}

// ---------------- distance bias (warp per row, fp16 out) --------------------
__global__ void dist_bias_k(const float* __restrict__ d, const float* __restrict__ scale_p,
                            __half* __restrict__ bias) {
    int row = blockIdx.x * 8 + (threadIdx.x >> 5);
    int lane = threadIdx.x & 31;
    const float* dp = d + (long long)row * SS + lane * 4;
    float4 v[8];
    float mx = -1e30f;
    #pragma unroll
    for (int i = 0; i < 8; i++) {
        v[i] = *(const float4*)(dp + i * 128);
        mx = fmaxf(mx, fmaxf(fmaxf(v[i].x, v[i].y), fmaxf(v[i].z, v[i].w)));
    }
    mx = wrmax(mx);
    float inv_dmax = 1.f / mx;
    float sc = scale_p[0];
    __half* bp = bias + (long long)row * SS + lane * 4;
    #pragma unroll
    for (int i = 0; i < 8; i++) {
        __half2 h0 = __halves2half2(__float2half_rn(expf(sc * (1.f - v[i].x * inv_dmax))),
                                    __float2half_rn(expf(sc * (1.f - v[i].y * inv_dmax))));
        __half2 h1 = __halves2half2(__float2half_rn(expf(sc * (1.f - v[i].z * inv_dmax))),
                                    __float2half_rn(expf(sc * (1.f - v[i].w * inv_dmax))));
        uint2 pk; pk.x = *reinterpret_cast<uint32_t*>(&h0); pk.y = *reinterpret_cast<uint32_t*>(&h1);
        *(uint2*)(bp + i * 128) = pk;
    }
}

// ---------------- softmax per head, head-avg, dist-bias, renorm (warp/row) --
__global__ void attn_w_k(const __half* __restrict__ scores, const __half* __restrict__ dbias,
                         __half* __restrict__ wh) {
    int row = blockIdx.x * 8 + (threadIdx.x >> 5);
    int lane = threadIdx.x & 31;
    int b = row >> 10, q = row & (SS - 1);
    float w[32];
    #pragma unroll
    for (int i = 0; i < 32; i++) w[i] = 0.f;
    const __half* sp = scores + ((long long)b * HH * SS + q) * SS + lane * 8;
    #pragma unroll 1
    for (int h = 0; h < HH; h++) {
        const __half* p = sp + (long long)h * SS * SS;
        float v[32];
        float mx = -1e30f;
        #pragma unroll
        for (int i = 0; i < 4; i++) {
            uint4 raw = *(const uint4*)(p + i * 256);
            float2 f0 = __half22float2(*reinterpret_cast<__half2*>(&raw.x));
            float2 f1 = __half22float2(*reinterpret_cast<__half2*>(&raw.y));
            float2 f2 = __half22float2(*reinterpret_cast<__half2*>(&raw.z));
            float2 f3 = __half22float2(*reinterpret_cast<__half2*>(&raw.w));
            v[i*8+0]=f0.x; v[i*8+1]=f0.y; v[i*8+2]=f1.x; v[i*8+3]=f1.y;
            v[i*8+4]=f2.x; v[i*8+5]=f2.y; v[i*8+6]=f3.x; v[i*8+7]=f3.y;
            #pragma unroll
            for (int e = 0; e < 8; e++) mx = fmaxf(mx, v[i*8+e]);
        }
        mx = wrmax(mx);
        float ls = 0.f;
        #pragma unroll
        for (int i = 0; i < 32; i++) { v[i] = __expf(v[i] - mx); ls += v[i]; }
        float inv = 1.f / wrsum(ls);
        #pragma unroll
        for (int i = 0; i < 32; i++) w[i] += v[i] * inv;
    }
    const __half* dbp = dbias + (long long)row * SS + lane * 8;
    float ls = 0.f;
    #pragma unroll
    for (int i = 0; i < 4; i++) {
        uint4 raw = *(const uint4*)(dbp + i * 256);
        float2 f0 = __half22float2(*reinterpret_cast<__half2*>(&raw.x));
        float2 f1 = __half22float2(*reinterpret_cast<__half2*>(&raw.y));
        float2 f2 = __half22float2(*reinterpret_cast<__half2*>(&raw.z));
        float2 f3 = __half22float2(*reinterpret_cast<__half2*>(&raw.w));
        w[i*8+0]*=f0.x; w[i*8+1]*=f0.y; w[i*8+2]*=f1.x; w[i*8+3]*=f1.y;
        w[i*8+4]*=f2.x; w[i*8+5]*=f2.y; w[i*8+6]*=f3.x; w[i*8+7]*=f3.y;
        #pragma unroll
        for (int e = 0; e < 8; e++) ls += w[i*8+e];
    }
    float inv = 1.f / wrsum(ls);
    __half* wp = wh + (long long)row * SS + lane * 8;
    #pragma unroll
    for (int i = 0; i < 4; i++) {
        __half2 h0 = __halves2half2(__float2half_rn(w[i*8+0]*inv), __float2half_rn(w[i*8+1]*inv));
        __half2 h1 = __halves2half2(__float2half_rn(w[i*8+2]*inv), __float2half_rn(w[i*8+3]*inv));
        __half2 h2 = __halves2half2(__float2half_rn(w[i*8+4]*inv), __float2half_rn(w[i*8+5]*inv));
        __half2 h3 = __halves2half2(__float2half_rn(w[i*8+6]*inv), __float2half_rn(w[i*8+7]*inv));
        uint4 pk;
        pk.x = *reinterpret_cast<uint32_t*>(&h0); pk.y = *reinterpret_cast<uint32_t*>(&h1);
        pk.z = *reinterpret_cast<uint32_t*>(&h2); pk.w = *reinterpret_cast<uint32_t*>(&h3);
        *(uint4*)(wp + i * 256) = pk;
    }
}

// ---------------- fused residual + LayerNorm (warp per row) -----------------
template<bool SPLIT>
__global__ void add_ln_k(const float* __restrict__ x, const float* __restrict__ r,
                         const float* __restrict__ g, const float* __restrict__ b,
                         float* __restrict__ out, __half* __restrict__ oh) {
    int row = blockIdx.x * 8 + (threadIdx.x >> 5);
    int lane = threadIdx.x & 31;
    long long base = (long long)row * EE + lane * 4;
    float4 v[4];
    float s = 0.f, sq = 0.f;
    #pragma unroll
    for (int i = 0; i < 4; i++) {
        float4 a = *(const float4*)(x + base + i * 128);
        float4 rr = *(const float4*)(r + base + i * 128);
        a.x += rr.x; a.y += rr.y; a.z += rr.z; a.w += rr.w;
        v[i] = a;
        s += a.x + a.y + a.z + a.w;
        sq += a.x*a.x + a.y*a.y + a.z*a.z + a.w*a.w;
    }
    float mean = wrsum(s) * (1.f / (float)EE);
    float var = wrsum(sq) * (1.f / (float)EE) - mean * mean;
    float inv = rsqrtf(var + EPS);
    #pragma unroll
    for (int i = 0; i < 4; i++) {
        float4 gg = *(const float4*)(g + lane * 4 + i * 128);
        float4 bb = *(const float4*)(b + lane * 4 + i * 128);
        float4 o;
        o.x = (v[i].x - mean) * inv * gg.x + bb.x;
        o.y = (v[i].y - mean) * inv * gg.y + bb.y;
        o.z = (v[i].z - mean) * inv * gg.z + bb.z;
        o.w = (v[i].w - mean) * inv * gg.w + bb.w;
        *(float4*)(out + base + i * 128) = o;
        if (SPLIT) {
            __half2 h0 = __halves2half2(__float2half_rn(o.x), __float2half_rn(o.y));
            __half2 h1 = __halves2half2(__float2half_rn(o.z), __float2half_rn(o.w));
            uint2 pk; pk.x = *reinterpret_cast<uint32_t*>(&h0); pk.y = *reinterpret_cast<uint32_t*>(&h1);
            *(uint2*)(oh + base + i * 128) = pk;
        }
    }
}

// ---------------- launch -----------------------------------------------------
extern "C" void kernel_launch(void* const* d_in, const int* in_sizes, int n_in,
                              void* d_out, int out_size) {
    (void)in_sizes; (void)n_in; (void)out_size;
    const float* src        = (const float*)d_in[0];
    const float* distances  = (const float*)d_in[1];
    const float* proj_w     = (const float*)d_in[2];
    const float* proj_b     = (const float*)d_in[3];
    const float* bn_g       = (const float*)d_in[4];
    const float* bn_b       = (const float*)d_in[5];
    const float* in_proj_w  = (const float*)d_in[6];
    const float* in_proj_b  = (const float*)d_in[7];
    const float* dist_scale = (const float*)d_in[8];
    const float* lin1_w     = (const float*)d_in[9];
    const float* lin1_b     = (const float*)d_in[10];
    const float* lin2_w     = (const float*)d_in[11];
    const float* lin2_b     = (const float*)d_in[12];
    const float* n1_g       = (const float*)d_in[13];
    const float* n1_b       = (const float*)d_in[14];
    const float* n2_g       = (const float*)d_in[15];
    const float* n2_b       = (const float*)d_in[16];
    float* out = (float*)d_out;

    float *x, *attn, *part, *stats;
    __half *sc, *dbias, *srch, *srcl, *xh, *qkh, *wh, *ffh;
    __half *pwh, *pwl, *iph, *l1h, *l2h;
    cudaGetSymbolAddress((void**)&x,     g_x);
    cudaGetSymbolAddress((void**)&sc,    g_scores);
    cudaGetSymbolAddress((void**)&dbias, g_dbias);
    cudaGetSymbolAddress((void**)&attn,  g_attn);
    cudaGetSymbolAddress((void**)&part,  g_part);
    cudaGetSymbolAddress((void**)&stats, g_stats);
    cudaGetSymbolAddress((void**)&srch,  g_srch); cudaGetSymbolAddress((void**)&srcl, g_srcl);
    cudaGetSymbolAddress((void**)&xh,    g_xh);
    cudaGetSymbolAddress((void**)&qkh,   g_qkh);
    cudaGetSymbolAddress((void**)&wh,    g_wh);
    cudaGetSymbolAddress((void**)&ffh,   g_ffh);
    cudaGetSymbolAddress((void**)&pwh,   g_pwh);  cudaGetSymbolAddress((void**)&pwl,  g_pwl);
    cudaGetSymbolAddress((void**)&iph,   g_iph);
    cudaGetSymbolAddress((void**)&l1h,   g_l1h);
    cudaGetSymbolAddress((void**)&l2h,   g_l2h);

    cudaFuncSetAttribute(gemm_mma<false,true,true,0,false>,   cudaFuncAttributeMaxDynamicSharedMemorySize, GEMM_SMEM);
    cudaFuncSetAttribute(gemm_mma<false,false,false,2,false>, cudaFuncAttributeMaxDynamicSharedMemorySize, GEMM_SMEM);
    cudaFuncSetAttribute(gemm_mma<false,false,false,2,true>,  cudaFuncAttributeMaxDynamicSharedMemorySize, GEMM_SMEM);
    cudaFuncSetAttribute(gemm_mma<true,false,false,0,false>,  cudaFuncAttributeMaxDynamicSharedMemorySize, GEMM_SMEM);
    cudaFuncSetAttribute(gemm_mma<false,false,false,0,false>, cudaFuncAttributeMaxDynamicSharedMemorySize, GEMM_SMEM);

    dim3 blk(256);
    const long long SE  = (long long)SS * EE;
    const long long SQ  = (long long)SS * 1024;
    const long long SS2 = (long long)SS * SS;

    // 0) one-time conversions
    split_k<<<(ROWS*IN_F+255)/256, 256>>>(src, srch, srcl, ROWS*IN_F);
    split_k<<<(EE*IN_F+255)/256, 256>>>(proj_w, pwh, pwl, EE*IN_F);
    cvt_k<<<(1024*EE+255)/256, 256>>>(in_proj_w, iph, 1024*EE);   // q,k rows only
    cvt_k<<<(FF_DIM*EE+255)/256, 256>>>(lin1_w, l1h, FF_DIM*EE);
    cvt_k<<<(EE*FF_DIM+255)/256, 256>>>(lin2_w, l2h, EE*FF_DIM);

    // 1) input projection -> g_x (fp32), 3-pass (feeds BN stats; cheap)
    gemm_mma<false,true,true,0,false><<<dim3(EE/128, ROWS/128, 1), blk, GEMM_SMEM>>>(
        srch, srcl, pwh, pwl, proj_b, x, nullptr,
        IN_F, IN_F, IN_F, EE, 1, 0, 0, 0, 0, 0, 1.f);

    // 2) BatchNorm (batch stats) + PE (+fp16 mirror)
    bn_part_k<<<64, 512>>>(x, part);
    bn_final_k<<<2, 256>>>(part, stats);
    bn_apply_pe_k<<<(ROWS*EE)/256, 256>>>(x, stats, bn_g, bn_b, xh);

    // 3) distance bias (fp16, shared across layers)
    dist_bias_k<<<BB*SS/8, 256>>>(distances, dist_scale, dbias);

    // 4) layers (shared parameters) — all layer GEMMs single-pass fp16
    for (int l = 0; l < NL; l++) {
        // qk = x @ in_proj_w[0:1024]^T + b  -> fp16
        gemm_mma<false,false,false,2,false><<<dim3(1024/128, ROWS/128, 1), blk, GEMM_SMEM>>>(
            xh, nullptr, iph, nullptr, in_proj_b, nullptr, qkh,
            EE, EE, EE, 1024, 1, 0, 0, 0, 0, 0, 1.f);

        // scores[b,h] = (Q_bh @ K_bh^T) * 1/sqrt(HD) -> fp16
        gemm_mma<false,false,false,2,false><<<dim3(SS/128, SS/128, BB*HH), blk, GEMM_SMEM>>>(
            qkh, nullptr, qkh + EE, nullptr, nullptr, nullptr, sc,
            HD, 1024, 1024, SS, HH, SQ, HD, SQ, HD, SS2, 0.125f);

        // softmax/head-avg/dist-bias/renorm -> fp16 w (warp per row)
        attn_w_k<<<BB*SS/8, 256>>>(sc, dbias, wh);

        // attn_out = w @ x -> fp32
        gemm_mma<true,false,false,0,false><<<dim3(EE/128, SS/128, BB), blk, GEMM_SMEM>>>(
            wh, nullptr, xh, nullptr, nullptr, attn, nullptr,
            SS, SS, EE, EE, 1, SS2, 0, SE, 0, SE, 1.f);

        // x = LN(x + attn_out) (+fp16 mirror)
        add_ln_k<true><<<ROWS/8, 256>>>(x, attn, n1_g, n1_b, x, xh);

        // FFN
        gemm_mma<false,false,false,2,true><<<dim3(FF_DIM/128, ROWS/128, 1), blk, GEMM_SMEM>>>(
            xh, nullptr, l1h, nullptr, lin1_b, nullptr, ffh,
            EE, EE, EE, FF_DIM, 1, 0, 0, 0, 0, 0, 1.f);
        gemm_mma<false,false,false,0,false><<<dim3(EE/128, ROWS/128, 1), blk, GEMM_SMEM>>>(
            ffh, nullptr, l2h, nullptr, lin2_b, attn, nullptr,
            FF_DIM, FF_DIM, FF_DIM, EE, 1, 0, 0, 0, 0, 0, 1.f);

        // x = LN(x + ff); last layer -> d_out
        if (l == NL - 1)
            add_ln_k<false><<<ROWS/8, 256>>>(x, attn, n2_g, n2_b, out, nullptr);
        else
            add_ln_k<true><<<ROWS/8, 256>>>(x, attn, n2_g, n2_b, x, xh);
    }
}